// round 10
// baseline (speedup 1.0000x reference)
#include <cuda_runtime.h>
#include <cuda_bf16.h>
#include <math.h>
#include <stdint.h>

#define D_MODEL 2048
#define NHEADS  16
#define DHEAD   128
#define SEQLEN  2048
#define BATCH   2
#define MROWS   (BATCH*SEQLEN)   // 4096
#define QK_SCALE 0.08838834764831845f   // 1/sqrt(128)

// ---------------- scratch (device globals; no allocation allowed) ----------------
__device__ float g_cos[SEQLEN*(DHEAD/2)];
__device__ float g_sin[SEQLEN*(DHEAD/2)];

__device__ __nv_bfloat16 g_xhi[MROWS*D_MODEL];
__device__ __nv_bfloat16 g_xlo[MROWS*D_MODEL];
__device__ __nv_bfloat16 g_whi[4][D_MODEL*D_MODEL];   // 0=Wq 1=Wk 2=Wv 3=Wo
__device__ __nv_bfloat16 g_wlo[4][D_MODEL*D_MODEL];
__device__ __nv_bfloat16 g_ahi[MROWS*D_MODEL];        // attention out, x-layout
__device__ __nv_bfloat16 g_alo[MROWS*D_MODEL];
__device__ __nv_bfloat16 g_qhi[BATCH*NHEADS*SEQLEN*DHEAD];
__device__ __nv_bfloat16 g_qlo[BATCH*NHEADS*SEQLEN*DHEAD];
__device__ __nv_bfloat16 g_khi[BATCH*NHEADS*SEQLEN*DHEAD];
__device__ __nv_bfloat16 g_klo[BATCH*NHEADS*SEQLEN*DHEAD];
__device__ __nv_bfloat16 g_vhi[BATCH*NHEADS*SEQLEN*DHEAD];
__device__ __nv_bfloat16 g_vlo[BATCH*NHEADS*SEQLEN*DHEAD];

// ---------------- PTX helpers (sm_80-level only) -----------------------------------
__device__ __forceinline__ uint32_t smem_u32(const void* p) {
    uint32_t a;
    asm("{ .reg .u64 t; cvta.to.shared.u64 t, %1; cvt.u32.u64 %0, t; }" : "=r"(a) : "l"(p));
    return a;
}
__device__ __forceinline__ void cp16(uint32_t dst, const void* src) {
    asm volatile("cp.async.cg.shared.global [%0], [%1], 16;" :: "r"(dst), "l"(src));
}
#define CP_COMMIT() asm volatile("cp.async.commit_group;" ::: "memory")
#define CP_WAIT(n)  asm volatile("cp.async.wait_group %0;" :: "n"(n) : "memory")

__device__ __forceinline__ void ldm_x4(uint32_t* r, uint32_t addr) {
    asm volatile("ldmatrix.sync.aligned.m8n8.x4.shared.b16 {%0,%1,%2,%3}, [%4];"
                 : "=r"(r[0]), "=r"(r[1]), "=r"(r[2]), "=r"(r[3]) : "r"(addr));
}
__device__ __forceinline__ void ldm_x4_t(uint32_t* r, uint32_t addr) {
    asm volatile("ldmatrix.sync.aligned.m8n8.x4.trans.shared.b16 {%0,%1,%2,%3}, [%4];"
                 : "=r"(r[0]), "=r"(r[1]), "=r"(r[2]), "=r"(r[3]) : "r"(addr));
}
__device__ __forceinline__ void mma_bf16(float* c, const uint32_t* a, uint32_t b0, uint32_t b1) {
    asm volatile("mma.sync.aligned.m16n8k16.row.col.f32.bf16.bf16.f32 "
                 "{%0,%1,%2,%3}, {%4,%5,%6,%7}, {%8,%9}, {%0,%1,%2,%3};"
                 : "+f"(c[0]), "+f"(c[1]), "+f"(c[2]), "+f"(c[3])
                 : "r"(a[0]), "r"(a[1]), "r"(a[2]), "r"(a[3]), "r"(b0), "r"(b1));
}
__device__ __forceinline__ uint32_t packbf2(float lo, float hi) {
    uint32_t r;
    asm("cvt.rn.bf16x2.f32 %0, %1, %2;" : "=r"(r) : "f"(hi), "f"(lo));
    return r;
}

// ---------------- RoPE tables ------------------------------------------------------
__global__ void rope_table_kernel() {
    int idx = blockIdx.x * blockDim.x + threadIdx.x;
    int pos = idx >> 6;
    int p   = idx & 63;
    double freq = exp(-((double)(2 * p) / 128.0) * log(10000.0));
    double ang  = (double)pos * freq;
    g_cos[idx] = (float)cos(ang);
    g_sin[idx] = (float)sin(ang);
}

// ---------------- hi/lo bf16 split kernels -----------------------------------------
__global__ void split_x_kernel(const float* __restrict__ src) {
    int i = blockIdx.x * 256 + threadIdx.x;
    float v = src[i];
    __nv_bfloat16 h = __float2bfloat16(v);
    g_xhi[i] = h;
    g_xlo[i] = __float2bfloat16(v - __bfloat162float(h));
}
__global__ void split_w_kernel(const float* __restrict__ w0, const float* __restrict__ w1,
                               const float* __restrict__ w2, const float* __restrict__ w3) {
    int i = blockIdx.x * 256 + threadIdx.x;
    int wsel = blockIdx.y;
    const float* s = (wsel == 0) ? w0 : (wsel == 1) ? w1 : (wsel == 2) ? w2 : w3;
    float v = s[i];
    __nv_bfloat16 h = __float2bfloat16(v);
    g_whi[wsel][i] = h;
    g_wlo[wsel][i] = __float2bfloat16(v - __bfloat162float(h));
}

// ---------------- mma.sync split-bf16 GEMM core: 64x64 warp tiles ------------------
// BM=BN=128, BK=16, 128 threads (4 warps, 2m x 2n), 4-stage pipe, occupancy 2.
// Per warp-stage: 16 LDSM (8KB) for 32 useful MMAs -> 16 FLOP/smem-byte (1.5x R9).
#define GLD 24
#define T_A_HI 0
#define T_A_LO (128*GLD)
#define T_B_HI (2*128*GLD)
#define T_B_LO (3*128*GLD)
#define STAGE_HALVES (4*128*GLD)              // 12288 halves = 24576 B
#define SMEM_GEMM_BYTES (4*STAGE_HALVES*2)    // 98304 B

struct GemmCore {
    uint32_t sb;
    int lane, wm, wn, lr, lh;
    const __nv_bfloat16 *pAh, *pAl, *pBh, *pBl;

    __device__ __forceinline__ void init(uint32_t sb_, int m0, int n0,
                                         const __nv_bfloat16* Ahi, const __nv_bfloat16* Alo,
                                         const __nv_bfloat16* Bhi, const __nv_bfloat16* Blo) {
        sb = sb_;
        int tid = threadIdx.x;
        lane = tid & 31;
        int warp = tid >> 5;
        wm = warp & 1; wn = warp >> 1;
        lr = lane & 15; lh = lane >> 4;
        pAh = Ahi + (size_t)(m0 + tid) * 2048;
        pAl = Alo + (size_t)(m0 + tid) * 2048;
        pBh = Bhi + (size_t)(n0 + tid) * 2048;
        pBl = Blo + (size_t)(n0 + tid) * 2048;
    }
    __device__ __forceinline__ void load_stage(int s, int buf) {
        const int tid = threadIdx.x;
        const uint32_t base = sb + buf * STAGE_HALVES * 2;
        #pragma unroll
        for (int c = 0; c < 2; c++) {
            const int ks = s * 16 + c * 8;
            const uint32_t off = (tid * GLD + c * 8) * 2;
            cp16(base + T_A_HI*2 + off, pAh + ks);
            cp16(base + T_A_LO*2 + off, pAl + ks);
            cp16(base + T_B_HI*2 + off, pBh + ks);
            cp16(base + T_B_LO*2 + off, pBl + ks);
        }
    }
    __device__ __forceinline__ void run(float acc[4][8][4]) {
        load_stage(0, 0); CP_COMMIT();
        load_stage(1, 1); CP_COMMIT();
        load_stage(2, 2); CP_COMMIT();
        for (int s = 0; s < 128; s++) {
            if (s + 3 < 128) { load_stage(s + 3, (s + 3) & 3); CP_COMMIT(); }
            if      (s < 125)  CP_WAIT(3);
            else if (s == 125) CP_WAIT(2);
            else if (s == 126) CP_WAIT(1);
            else               CP_WAIT(0);
            __syncthreads();
            const uint32_t base = sb + (s & 3) * STAGE_HALVES * 2;
            uint32_t ah[4][4], al[4][4], bh[4][4], bl[4][4];
            #pragma unroll
            for (int mf = 0; mf < 4; mf++) {
                uint32_t ra = base + ((wm*64 + mf*16 + lr) * GLD + lh*8) * 2;
                ldm_x4(ah[mf], ra + T_A_HI*2);
                ldm_x4(al[mf], ra + T_A_LO*2);
            }
            #pragma unroll
            for (int nb = 0; nb < 4; nb++) {
                uint32_t rb = base + ((wn*64 + nb*16 + lr) * GLD + lh*8) * 2;
                ldm_x4(bh[nb], rb + T_B_HI*2);
                ldm_x4(bl[nb], rb + T_B_LO*2);
            }
            #pragma unroll
            for (int mf = 0; mf < 4; mf++)
                #pragma unroll
                for (int nb = 0; nb < 4; nb++)
                    #pragma unroll
                    for (int sub = 0; sub < 2; sub++) {
                        float* c = acc[mf][nb*2 + sub];
                        mma_bf16(c, ah[mf], bh[nb][sub], bh[nb][sub+2]);
                        mma_bf16(c, ah[mf], bl[nb][sub], bl[nb][sub+2]);
                        mma_bf16(c, al[mf], bh[nb][sub], bh[nb][sub+2]);
                    }
            __syncthreads();
        }
    }
};

// ---- fused Q/K/V projection: grid (16, 32, 3), z: 0=Q 1=K 2=V ----------------------
__global__ void __launch_bounds__(128, 2)
qkv_mma(const float* __restrict__ bq, const float* __restrict__ bk,
        const float* __restrict__ bv)
{
    extern __shared__ __nv_bfloat16 smem[];
    const int m0 = blockIdx.y * 128;
    const int n0 = blockIdx.x * 128;
    const int z  = blockIdx.z;

    GemmCore core;
    core.init(smem_u32(smem), m0, n0, g_xhi, g_xlo, g_whi[z], g_wlo[z]);

    float acc[4][8][4];
    #pragma unroll
    for (int i = 0; i < 4; i++)
        #pragma unroll
        for (int j = 0; j < 8; j++)
            #pragma unroll
            for (int k = 0; k < 4; k++) acc[i][j][k] = 0.f;

    core.run(acc);

    const float* bias = (z == 0) ? bq : (z == 1) ? bk : bv;
    __nv_bfloat16* dhi = (z == 0) ? g_qhi : (z == 1) ? g_khi : g_vhi;
    __nv_bfloat16* dlo = (z == 0) ? g_qlo : (z == 1) ? g_klo : g_vlo;
    const bool do_rope = (z != 2);
    const float sc = (z == 0) ? QK_SCALE : 1.0f;

    const int g = core.lane >> 2, t = core.lane & 3;
    #pragma unroll
    for (int mf = 0; mf < 4; mf++) {
        const int r0 = m0 + core.wm*64 + mf*16 + g;
        const int r1 = r0 + 8;
        const int bb0 = r0 >> 11, pos0 = r0 & 2047;
        const int bb1 = r1 >> 11, pos1 = r1 & 2047;
        #pragma unroll
        for (int nf = 0; nf < 8; nf++) {
            const int col = n0 + core.wn*64 + nf*8 + 2*t;
            float b0 = bias[col], b1 = bias[col + 1];
            float v00 = acc[mf][nf][0] + b0, v01 = acc[mf][nf][1] + b1;
            float v10 = acc[mf][nf][2] + b0, v11 = acc[mf][nf][3] + b1;
            if (do_rope) {
                const int p = (col & 127) >> 1;
                float cs0 = g_cos[pos0*64 + p], sn0 = g_sin[pos0*64 + p];
                float cs1 = g_cos[pos1*64 + p], sn1 = g_sin[pos1*64 + p];
                float x1 = v00, x2 = v01;
                v00 = (x1*cs0 - x2*sn0) * sc;  v01 = (x1*sn0 + x2*cs0) * sc;
                x1 = v10; x2 = v11;
                v10 = (x1*cs1 - x2*sn1) * sc;  v11 = (x1*sn1 + x2*cs1) * sc;
            }
            const int h = col >> 7, d = col & 127;
            size_t base0 = (((size_t)(bb0*NHEADS + h) * SEQLEN + pos0) * DHEAD + d);
            size_t base1 = (((size_t)(bb1*NHEADS + h) * SEQLEN + pos1) * DHEAD + d);
            __nv_bfloat16 h00 = __float2bfloat16(v00), h01 = __float2bfloat16(v01);
            __nv_bfloat16 h10 = __float2bfloat16(v10), h11 = __float2bfloat16(v11);
            __nv_bfloat162 hp0; hp0.x = h00; hp0.y = h01;
            __nv_bfloat162 hp1; hp1.x = h10; hp1.y = h11;
            *(__nv_bfloat162*)(dhi + base0) = hp0;
            *(__nv_bfloat162*)(dhi + base1) = hp1;
            __nv_bfloat162 lp0, lp1;
            lp0.x = __float2bfloat16(v00 - __bfloat162float(h00));
            lp0.y = __float2bfloat16(v01 - __bfloat162float(h01));
            lp1.x = __float2bfloat16(v10 - __bfloat162float(h10));
            lp1.y = __float2bfloat16(v11 - __bfloat162float(h11));
            *(__nv_bfloat162*)(dlo + base0) = lp0;
            *(__nv_bfloat162*)(dlo + base1) = lp1;
        }
    }
}

// ---- output projection -------------------------------------------------------------
__global__ void __launch_bounds__(128, 2)
out_mma(const float* __restrict__ bias, float* __restrict__ outp)
{
    extern __shared__ __nv_bfloat16 smem[];
    const int m0 = blockIdx.y * 128;
    const int n0 = blockIdx.x * 128;

    GemmCore core;
    core.init(smem_u32(smem), m0, n0, g_ahi, g_alo, g_whi[3], g_wlo[3]);

    float acc[4][8][4];
    #pragma unroll
    for (int i = 0; i < 4; i++)
        #pragma unroll
        for (int j = 0; j < 8; j++)
            #pragma unroll
            for (int k = 0; k < 4; k++) acc[i][j][k] = 0.f;

    core.run(acc);

    const int g = core.lane >> 2, t = core.lane & 3;
    #pragma unroll
    for (int mf = 0; mf < 4; mf++) {
        const int r0 = m0 + core.wm*64 + mf*16 + g;
        const int r1 = r0 + 8;
        #pragma unroll
        for (int nf = 0; nf < 8; nf++) {
            const int col = n0 + core.wn*64 + nf*8 + 2*t;
            float b0 = bias[col], b1 = bias[col + 1];
            *(float2*)(outp + (size_t)r0 * 2048 + col) =
                make_float2(acc[mf][nf][0] + b0, acc[mf][nf][1] + b1);
            *(float2*)(outp + (size_t)r1 * 2048 + col) =
                make_float2(acc[mf][nf][2] + b0, acc[mf][nf][3] + b1);
        }
    }
}

// ---------------- tensor-core flash attention, occupancy 2 (unchanged R9) ----------
#define AKVLD 136
#define A_SUB 8704
#define A_KH(b) ((b)*2*A_SUB)
#define A_KL(b) ((b)*2*A_SUB + A_SUB)
#define A_VH   (4*A_SUB)
#define A_VL   (5*A_SUB)
#define SM_ATTN_BYTES (6*A_SUB*2)        // 104448 B

__global__ void __launch_bounds__(128, 2)
attn_mma()
{
    extern __shared__ __nv_bfloat16 smn[];
    const uint32_t sb = smem_u32(smn);
    const int tid = threadIdx.x, lane = tid & 31, w = tid >> 5;
    const int bh = blockIdx.y;
    const int qt = 31 - blockIdx.x;
    const int q0 = qt * 64;

    const size_t qoff = ((size_t)bh * SEQLEN + q0) * DHEAD;
    for (int idx = tid; idx < 1024; idx += 128) {
        int row = idx >> 4, c = idx & 15;
        uint32_t off = (uint32_t)(row * AKVLD + c * 8) * 2;
        cp16(sb + A_KH(0)*2 + off, g_qhi + qoff + row * 128 + c * 8);
        cp16(sb + A_KL(0)*2 + off, g_qlo + qoff + row * 128 + c * 8);
    }
    CP_COMMIT(); CP_WAIT(0);
    __syncthreads();

    uint32_t qh[8][4], ql[8][4];
    const int lr = lane & 15, lhb = lane >> 4;
    #pragma unroll
    for (int kk = 0; kk < 8; kk++) {
        uint32_t ra = sb + (uint32_t)((w*16 + lr) * AKVLD + kk*16 + lhb*8) * 2;
        ldm_x4(qh[kk], ra + A_KH(0)*2);
        ldm_x4(ql[kk], ra + A_KL(0)*2);
    }
    __syncthreads();

    auto load_K = [&](int jt, int buf) {
        const size_t koff = ((size_t)bh * SEQLEN + jt * 64) * DHEAD;
        for (int idx = tid; idx < 1024; idx += 128) {
            int row = idx >> 4, c = idx & 15;
            uint32_t off = (uint32_t)(row * AKVLD + c * 8) * 2;
            int so = row * 128 + c * 8;
            cp16(sb + A_KH(buf)*2 + off, g_khi + koff + so);
            cp16(sb + A_KL(buf)*2 + off, g_klo + koff + so);
        }
    };
    auto load_V = [&](int jt) {
        const size_t koff = ((size_t)bh * SEQLEN + jt * 64) * DHEAD;
        for (int idx = tid; idx < 1024; idx += 128) {
            int row = idx >> 4, c = idx & 15;
            uint32_t off = (uint32_t)(row * AKVLD + c * 8) * 2;
            int so = row * 128 + c * 8;
            cp16(sb + A_VH*2 + off, g_vhi + koff + so);
            cp16(sb + A_VL*2 + off, g_vlo + koff + so);
        }
    };

    float m_[2] = {-INFINITY, -INFINITY};
    float l_[2] = {0.f, 0.f};
    float o[16][4];
    #pragma unroll
    for (int i = 0; i < 16; i++)
        #pragma unroll
        for (int j = 0; j < 4; j++) o[i][j] = 0.f;

    const int g  = lane >> 2, t2 = (lane & 3) * 2;
    const int wrow0 = q0 + w * 16;
    const int row0  = wrow0 + g;

    const int ntiles = qt + 1;
    load_K(0, 0); CP_COMMIT();
    load_V(0);    CP_COMMIT();

    for (int jt = 0; jt < ntiles; jt++) {
        const int kbuf = jt & 1;
        const int kv0 = jt * 64;
        const bool more = (jt + 1 < ntiles);

        if (more) { load_K(jt + 1, kbuf ^ 1); CP_COMMIT(); }
        if (more) CP_WAIT(2); else CP_WAIT(1);
        __syncthreads();

        const uint32_t kb = sb + A_KH(kbuf) * 2;

        float s[8][4];
        #pragma unroll
        for (int i = 0; i < 8; i++)
            #pragma unroll
            for (int j = 0; j < 4; j++) s[i][j] = 0.f;

        #pragma unroll
        for (int kk = 0; kk < 8; kk++) {
            #pragma unroll
            for (int nb = 0; nb < 4; nb++) {
                uint32_t kh4[4], kl4[4];
                uint32_t rb = kb + (uint32_t)((nb*16 + lr) * AKVLD + kk*16 + lhb*8) * 2;
                ldm_x4(kh4, rb);
                ldm_x4(kl4, rb + A_SUB*2);
                #pragma unroll
                for (int sub = 0; sub < 2; sub++) {
                    float* c = s[nb*2 + sub];
                    mma_bf16(c, qh[kk], kh4[sub], kh4[sub+2]);
                    mma_bf16(c, qh[kk], kl4[sub], kl4[sub+2]);
                    mma_bf16(c, ql[kk], kh4[sub], kh4[sub+2]);
                }
            }
        }

        if (kv0 + 63 > wrow0) {
            #pragma unroll
            for (int nf = 0; nf < 8; nf++) {
                int c0 = kv0 + nf*8 + t2;
                if (c0     > row0)     s[nf][0] = -1e30f;
                if (c0 + 1 > row0)     s[nf][1] = -1e30f;
                if (c0     > row0 + 8) s[nf][2] = -1e30f;
                if (c0 + 1 > row0 + 8) s[nf][3] = -1e30f;
            }
        }

        float mx0 = -INFINITY, mx1 = -INFINITY;
        #pragma unroll
        for (int nf = 0; nf < 8; nf++) {
            mx0 = fmaxf(mx0, fmaxf(s[nf][0], s[nf][1]));
            mx1 = fmaxf(mx1, fmaxf(s[nf][2], s[nf][3]));
        }
        mx0 = fmaxf(mx0, __shfl_xor_sync(0xffffffffu, mx0, 1));
        mx0 = fmaxf(mx0, __shfl_xor_sync(0xffffffffu, mx0, 2));
        mx1 = fmaxf(mx1, __shfl_xor_sync(0xffffffffu, mx1, 1));
        mx1 = fmaxf(mx1, __shfl_xor_sync(0xffffffffu, mx1, 2));
        float mn0 = fmaxf(m_[0], mx0), mn1 = fmaxf(m_[1], mx1);
        float f0 = __expf(m_[0] - mn0), f1 = __expf(m_[1] - mn1);
        m_[0] = mn0; m_[1] = mn1;

        float sum0 = 0.f, sum1 = 0.f;
        #pragma unroll
        for (int nf = 0; nf < 8; nf++) {
            s[nf][0] = __expf(s[nf][0] - mn0); sum0 += s[nf][0];
            s[nf][1] = __expf(s[nf][1] - mn0); sum0 += s[nf][1];
            s[nf][2] = __expf(s[nf][2] - mn1); sum1 += s[nf][2];
            s[nf][3] = __expf(s[nf][3] - mn1); sum1 += s[nf][3];
        }
        sum0 += __shfl_xor_sync(0xffffffffu, sum0, 1);
        sum0 += __shfl_xor_sync(0xffffffffu, sum0, 2);
        sum1 += __shfl_xor_sync(0xffffffffu, sum1, 1);
        sum1 += __shfl_xor_sync(0xffffffffu, sum1, 2);
        l_[0] = l_[0] * f0 + sum0;
        l_[1] = l_[1] * f1 + sum1;

        #pragma unroll
        for (int nf = 0; nf < 16; nf++) {
            o[nf][0] *= f0; o[nf][1] *= f0;
            o[nf][2] *= f1; o[nf][3] *= f1;
        }

        uint32_t ph[4][4], pl[4][4];
        #pragma unroll
        for (int kf = 0; kf < 4; kf++) {
            #pragma unroll
            for (int j = 0; j < 4; j++) {
                int nf = 2*kf + (j >> 1);
                int c0 = (j & 1) * 2;
                float p0 = s[nf][c0], p1 = s[nf][c0 + 1];
                __nv_bfloat16 b0 = __float2bfloat16(p0), b1 = __float2bfloat16(p1);
                __nv_bfloat162 hb; hb.x = b0; hb.y = b1;
                ph[kf][j] = *(uint32_t*)&hb;
                pl[kf][j] = packbf2(p0 - __bfloat162float(b0), p1 - __bfloat162float(b1));
            }
        }

        if (more) CP_WAIT(1); else CP_WAIT(0);
        __syncthreads();

        const uint32_t vbase = sb + A_VH * 2;
        const int matv = lane >> 3, jv = lane & 7;
        #pragma unroll
        for (int kf = 0; kf < 4; kf++) {
            #pragma unroll
            for (int ng = 0; ng < 8; ng++) {
                uint32_t vh4[4], vl4[4];
                uint32_t va = vbase + (uint32_t)((kf*16 + jv + ((matv & 1) << 3)) * AKVLD
                                                + ng*16 + ((matv >> 1) << 3)) * 2;
                ldm_x4_t(vh4, va);
                ldm_x4_t(vl4, va + A_SUB*2);
                #pragma unroll
                for (int sub = 0; sub < 2; sub++) {
                    float* c = o[ng*2 + sub];
                    mma_bf16(c, ph[kf], vh4[sub*2], vh4[sub*2+1]);
                    mma_bf16(c, ph[kf], vl4[sub*2], vl4[sub*2+1]);
                    mma_bf16(c, pl[kf], vh4[sub*2], vh4[sub*2+1]);
                }
            }
        }
        __syncthreads();
        if (more) { load_V(jt + 1); CP_COMMIT(); }
    }

    const float inv0 = 1.f / l_[0];
    const float inv1 = 1.f / l_[1];
    const int bb = bh >> 4, h = bh & 15;
    const size_t rA0 = (size_t)(bb * SEQLEN + row0) * D_MODEL + h * DHEAD;
    const size_t rA1 = rA0 + 8 * D_MODEL;
    #pragma unroll
    for (int nf = 0; nf < 16; nf++) {
        int d = nf*8 + t2;
        float v00 = o[nf][0]*inv0, v01 = o[nf][1]*inv0;
        float v10 = o[nf][2]*inv1, v11 = o[nf][3]*inv1;
        __nv_bfloat16 h00 = __float2bfloat16(v00), h01 = __float2bfloat16(v01);
        __nv_bfloat16 h10 = __float2bfloat16(v10), h11 = __float2bfloat16(v11);
        __nv_bfloat162 hp0; hp0.x = h00; hp0.y = h01;
        __nv_bfloat162 hp1; hp1.x = h10; hp1.y = h11;
        *(__nv_bfloat162*)(g_ahi + rA0 + d) = hp0;
        *(__nv_bfloat162*)(g_ahi + rA1 + d) = hp1;
        __nv_bfloat162 lp0, lp1;
        lp0.x = __float2bfloat16(v00 - __bfloat162float(h00));
        lp0.y = __float2bfloat16(v01 - __bfloat162float(h01));
        lp1.x = __float2bfloat16(v10 - __bfloat162float(h10));
        lp1.y = __float2bfloat16(v11 - __bfloat162float(h11));
        *(__nv_bfloat162*)(g_alo + rA0 + d) = lp0;
        *(__nv_bfloat162*)(g_alo + rA1 + d) = lp1;
    }
}

// ---------------- launch -----------------------------------------------------------
extern "C" void kernel_launch(void* const* d_in, const int* in_sizes, int n_in,
                              void* d_out, int out_size)
{
    const float* x  = (const float*)d_in[0];
    const float* Wq = (const float*)d_in[1];
    const float* bq = (const float*)d_in[2];
    const float* Wk = (const float*)d_in[3];
    const float* bk = (const float*)d_in[4];
    const float* Wv = (const float*)d_in[5];
    const float* bv = (const float*)d_in[6];
    const float* Wo = (const float*)d_in[7];
    const float* bo = (const float*)d_in[8];
    float* out = (float*)d_out;

    cudaFuncSetAttribute(attn_mma, cudaFuncAttributeMaxDynamicSharedMemorySize, SM_ATTN_BYTES);
    cudaFuncSetAttribute(qkv_mma,  cudaFuncAttributeMaxDynamicSharedMemorySize, SMEM_GEMM_BYTES);
    cudaFuncSetAttribute(out_mma,  cudaFuncAttributeMaxDynamicSharedMemorySize, SMEM_GEMM_BYTES);

    rope_table_kernel<<<512, 256>>>();

    const int NX = MROWS * D_MODEL;
    const int NW = D_MODEL * D_MODEL;
    split_x_kernel<<<NX/256, 256>>>(x);
    split_w_kernel<<<dim3(NW/256, 4), 256>>>(Wq, Wk, Wv, Wo);

    qkv_mma<<<dim3(16, 32, 3), 128, SMEM_GEMM_BYTES>>>(bq, bk, bv);

    attn_mma<<<dim3(32, 32), 128, SM_ATTN_BYTES>>>();

    out_mma<<<dim3(16, 32), 128, SMEM_GEMM_BYTES>>>(bo, out);
}

// round 11
// speedup vs baseline: 1.2044x; 1.2044x over previous
#include <cuda_runtime.h>
#include <cuda_bf16.h>
#include <cuda_fp16.h>
#include <math.h>
#include <stdint.h>

#define D_MODEL 2048
#define NHEADS  16
#define DHEAD   128
#define SEQLEN  2048
#define BATCH   2
#define MROWS   (BATCH*SEQLEN)   // 4096
#define QK_SCALE 0.08838834764831845f   // 1/sqrt(128)
#define SPLIT_SC 2048.0f                // 2^11 scaled-correction factor
#define SPLIT_SCI (1.0f/2048.0f)

// ---------------- scratch (device globals; no allocation allowed) ----------------
__device__ float g_cos[SEQLEN*(DHEAD/2)];
__device__ float g_sin[SEQLEN*(DHEAD/2)];

// bf16 3-term path (x, Wq, Wk -> Q, K)
__device__ __nv_bfloat16 g_xhi[MROWS*D_MODEL];
__device__ __nv_bfloat16 g_xlo[MROWS*D_MODEL];
__device__ __nv_bfloat16 g_whi[2][D_MODEL*D_MODEL];   // 0=Wq 1=Wk
__device__ __nv_bfloat16 g_wlo[2][D_MODEL*D_MODEL];
__device__ __nv_bfloat16 g_qhi[BATCH*NHEADS*SEQLEN*DHEAD];
__device__ __nv_bfloat16 g_qlo[BATCH*NHEADS*SEQLEN*DHEAD];
__device__ __nv_bfloat16 g_khi[BATCH*NHEADS*SEQLEN*DHEAD];
__device__ __nv_bfloat16 g_klo[BATCH*NHEADS*SEQLEN*DHEAD];

// fp16 2-term path (V-proj, PV, out-proj)
__device__ __half g_xf[MROWS*D_MODEL];                // fp16(x)
__device__ __half g_xs[MROWS*D_MODEL];                // fp16(x/2048)
__device__ __half g_wfh[2][D_MODEL*D_MODEL];          // 0=Wv 1=Wo : fp16(W)
__device__ __half g_wfl[2][D_MODEL*D_MODEL];          //          : fp16((W-hi)*2048)
__device__ __half g_vhf[BATCH*NHEADS*SEQLEN*DHEAD];   // fp16(v)
__device__ __half g_vlf[BATCH*NHEADS*SEQLEN*DHEAD];   // fp16((v-vh)*2048)
__device__ __half g_af[MROWS*D_MODEL];                // fp16(attn out)
__device__ __half g_as[MROWS*D_MODEL];                // fp16(attn out/2048)

// ---------------- PTX helpers (sm_80-level only) -----------------------------------
__device__ __forceinline__ uint32_t smem_u32(const void* p) {
    uint32_t a;
    asm("{ .reg .u64 t; cvta.to.shared.u64 t, %1; cvt.u32.u64 %0, t; }" : "=r"(a) : "l"(p));
    return a;
}
__device__ __forceinline__ void cp16(uint32_t dst, const void* src) {
    asm volatile("cp.async.cg.shared.global [%0], [%1], 16;" :: "r"(dst), "l"(src));
}
#define CP_COMMIT() asm volatile("cp.async.commit_group;" ::: "memory")
#define CP_WAIT(n)  asm volatile("cp.async.wait_group %0;" :: "n"(n) : "memory")

__device__ __forceinline__ void ldm_x4(uint32_t* r, uint32_t addr) {
    asm volatile("ldmatrix.sync.aligned.m8n8.x4.shared.b16 {%0,%1,%2,%3}, [%4];"
                 : "=r"(r[0]), "=r"(r[1]), "=r"(r[2]), "=r"(r[3]) : "r"(addr));
}
__device__ __forceinline__ void ldm_x4_t(uint32_t* r, uint32_t addr) {
    asm volatile("ldmatrix.sync.aligned.m8n8.x4.trans.shared.b16 {%0,%1,%2,%3}, [%4];"
                 : "=r"(r[0]), "=r"(r[1]), "=r"(r[2]), "=r"(r[3]) : "r"(addr));
}
__device__ __forceinline__ void mma_bf16(float* c, const uint32_t* a, uint32_t b0, uint32_t b1) {
    asm volatile("mma.sync.aligned.m16n8k16.row.col.f32.bf16.bf16.f32 "
                 "{%0,%1,%2,%3}, {%4,%5,%6,%7}, {%8,%9}, {%0,%1,%2,%3};"
                 : "+f"(c[0]), "+f"(c[1]), "+f"(c[2]), "+f"(c[3])
                 : "r"(a[0]), "r"(a[1]), "r"(a[2]), "r"(a[3]), "r"(b0), "r"(b1));
}
__device__ __forceinline__ void mma_fp16(float* c, const uint32_t* a, uint32_t b0, uint32_t b1) {
    asm volatile("mma.sync.aligned.m16n8k16.row.col.f32.f16.f16.f32 "
                 "{%0,%1,%2,%3}, {%4,%5,%6,%7}, {%8,%9}, {%0,%1,%2,%3};"
                 : "+f"(c[0]), "+f"(c[1]), "+f"(c[2]), "+f"(c[3])
                 : "r"(a[0]), "r"(a[1]), "r"(a[2]), "r"(a[3]), "r"(b0), "r"(b1));
}
__device__ __forceinline__ uint32_t packh2(float lo, float hi) {   // fp16x2, first asm src -> upper
    uint32_t r;
    asm("cvt.rn.f16x2.f32 %0, %1, %2;" : "=r"(r) : "f"(hi), "f"(lo));
    return r;
}

// ---------------- RoPE tables ------------------------------------------------------
__global__ void rope_table_kernel() {
    int idx = blockIdx.x * blockDim.x + threadIdx.x;
    int pos = idx >> 6;
    int p   = idx & 63;
    double freq = exp(-((double)(2 * p) / 128.0) * log(10000.0));
    double ang  = (double)pos * freq;
    g_cos[idx] = (float)cos(ang);
    g_sin[idx] = (float)sin(ang);
}

// ---------------- split kernels ----------------------------------------------------
__global__ void split_x_kernel(const float* __restrict__ src) {
    int i = blockIdx.x * 256 + threadIdx.x;
    float v = src[i];
    __nv_bfloat16 h = __float2bfloat16(v);
    g_xhi[i] = h;
    g_xlo[i] = __float2bfloat16(v - __bfloat162float(h));
    g_xf[i]  = __float2half(v);
    g_xs[i]  = __float2half(v * SPLIT_SCI);
}
// grid (NW/256, 4): 0=Wq(bf16) 1=Wk(bf16) 2=Wv(fp16) 3=Wo(fp16)
__global__ void split_w_kernel(const float* __restrict__ w0, const float* __restrict__ w1,
                               const float* __restrict__ w2, const float* __restrict__ w3) {
    int i = blockIdx.x * 256 + threadIdx.x;
    int wsel = blockIdx.y;
    const float* s = (wsel == 0) ? w0 : (wsel == 1) ? w1 : (wsel == 2) ? w2 : w3;
    float v = s[i];
    if (wsel < 2) {
        __nv_bfloat16 h = __float2bfloat16(v);
        g_whi[wsel][i] = h;
        g_wlo[wsel][i] = __float2bfloat16(v - __bfloat162float(h));
    } else {
        __half h = __float2half(v);
        g_wfh[wsel-2][i] = h;
        g_wfl[wsel-2][i] = __float2half((v - __half2float(h)) * SPLIT_SC);
    }
}

// ---------------- GEMM core: BM=BN=128, BK=16, 8 warps, 4-stage, 1 barrier/stage ---
// 3-term (bf16): A0=Ahi A1=Alo B0=Bhi B1=Blo ; 2-term (fp16): A0=af A1=as B0=Bh B1=Bl'
#define GLD 24
#define T_A0 0
#define T_A1 (128*GLD)
#define T_B0 (2*128*GLD)
#define T_B1 (3*128*GLD)
#define STAGE_HALVES (4*128*GLD)              // 24576 B
#define SMEM_GEMM_BYTES (4*STAGE_HALVES*2)    // 98304 B

struct GemmCore {
    uint32_t sb;
    int lane, wm, wn, lrow, lc, lr, lh;
    const uint16_t *pA0, *pA1, *pB0, *pB1;

    __device__ __forceinline__ void init(uint32_t sb_, int m0, int n0,
                                         const void* A0, const void* A1,
                                         const void* B0, const void* B1) {
        sb = sb_;
        int tid = threadIdx.x;
        lane = tid & 31;
        int warp = tid >> 5;
        wm = warp & 3; wn = warp >> 2;
        lrow = tid & 127; lc = tid >> 7;
        lr = lane & 15; lh = lane >> 4;
        pA0 = (const uint16_t*)A0 + (size_t)(m0 + lrow) * 2048;
        pA1 = (const uint16_t*)A1 + (size_t)(m0 + lrow) * 2048;
        pB0 = (const uint16_t*)B0 + (size_t)(n0 + lrow) * 2048;
        pB1 = (const uint16_t*)B1 + (size_t)(n0 + lrow) * 2048;
    }
    __device__ __forceinline__ void load_stage(int s, int buf) {
        const int ks = s * 16 + lc * 8;
        const uint32_t base = sb + buf * STAGE_HALVES * 2;
        const uint32_t off = (lrow * GLD + lc * 8) * 2;
        cp16(base + T_A0*2 + off, pA0 + ks);
        cp16(base + T_A1*2 + off, pA1 + ks);
        cp16(base + T_B0*2 + off, pB0 + ks);
        cp16(base + T_B1*2 + off, pB1 + ks);
    }
    template<int TERMS>
    __device__ __forceinline__ void run(float acc[2][8][4]) {
        load_stage(0, 0); CP_COMMIT();
        load_stage(1, 1); CP_COMMIT();
        load_stage(2, 2); CP_COMMIT();
        for (int s = 0; s < 128; s++) {
            const int rem = 127 - s;
            if      (rem >= 2) CP_WAIT(2);
            else if (rem == 1) CP_WAIT(1);
            else               CP_WAIT(0);
            __syncthreads();      // single barrier: 4-deep ring protects reuse
            const uint32_t base = sb + (s & 3) * STAGE_HALVES * 2;
            uint32_t a0[2][4], a1[2][4], b0[4][4], b1[4][4];
            #pragma unroll
            for (int mf = 0; mf < 2; mf++) {
                uint32_t ra = base + ((wm*32 + mf*16 + lr) * GLD + lh*8) * 2;
                ldm_x4(a0[mf], ra + T_A0*2);
                ldm_x4(a1[mf], ra + T_A1*2);
            }
            #pragma unroll
            for (int nb = 0; nb < 4; nb++) {
                uint32_t rb = base + ((wn*64 + nb*16 + lr) * GLD + lh*8) * 2;
                ldm_x4(b0[nb], rb + T_B0*2);
                ldm_x4(b1[nb], rb + T_B1*2);
            }
            #pragma unroll
            for (int mf = 0; mf < 2; mf++)
                #pragma unroll
                for (int nb = 0; nb < 4; nb++)
                    #pragma unroll
                    for (int sub = 0; sub < 2; sub++) {
                        float* c = acc[mf][nb*2 + sub];
                        if (TERMS == 3) {
                            mma_bf16(c, a0[mf], b0[nb][sub], b0[nb][sub+2]);
                            mma_bf16(c, a0[mf], b1[nb][sub], b1[nb][sub+2]);
                            mma_bf16(c, a1[mf], b0[nb][sub], b0[nb][sub+2]);
                        } else {
                            mma_fp16(c, a0[mf], b0[nb][sub], b0[nb][sub+2]);
                            mma_fp16(c, a1[mf], b1[nb][sub], b1[nb][sub+2]);
                        }
                    }
            if (s + 3 < 128) { load_stage(s + 3, (s + 3) & 3); CP_COMMIT(); }
        }
    }
};

// ---- fused Q/K/V projection: grid (16, 32, 3), z: 0=Q 1=K (3-term) 2=V (2-term) ----
__global__ void __launch_bounds__(256, 2)
qkv_mma(const float* __restrict__ bq, const float* __restrict__ bk,
        const float* __restrict__ bv)
{
    extern __shared__ __nv_bfloat16 smem[];
    const int m0 = blockIdx.y * 128;
    const int n0 = blockIdx.x * 128;
    const int z  = blockIdx.z;

    GemmCore core;
    float acc[2][8][4];
    #pragma unroll
    for (int i = 0; i < 2; i++)
        #pragma unroll
        for (int j = 0; j < 8; j++)
            #pragma unroll
            for (int k = 0; k < 4; k++) acc[i][j][k] = 0.f;

    if (z == 2) {
        core.init(smem_u32(smem), m0, n0, g_xf, g_xs, g_wfh[0], g_wfl[0]);
        core.run<2>(acc);
    } else {
        core.init(smem_u32(smem), m0, n0, g_xhi, g_xlo, g_whi[z], g_wlo[z]);
        core.run<3>(acc);
    }

    const float* bias = (z == 0) ? bq : (z == 1) ? bk : bv;
    const int g = core.lane >> 2, t = core.lane & 3;
    #pragma unroll
    for (int mf = 0; mf < 2; mf++) {
        const int r0 = m0 + core.wm*32 + mf*16 + g;
        const int r1 = r0 + 8;
        const int bb0 = r0 >> 11, pos0 = r0 & 2047;
        const int bb1 = r1 >> 11, pos1 = r1 & 2047;
        #pragma unroll
        for (int nf = 0; nf < 8; nf++) {
            const int col = n0 + core.wn*64 + nf*8 + 2*t;
            float b0 = bias[col], b1 = bias[col + 1];
            float v00 = acc[mf][nf][0] + b0, v01 = acc[mf][nf][1] + b1;
            float v10 = acc[mf][nf][2] + b0, v11 = acc[mf][nf][3] + b1;
            const int h = col >> 7, d = col & 127;
            size_t base0 = (((size_t)(bb0*NHEADS + h) * SEQLEN + pos0) * DHEAD + d);
            size_t base1 = (((size_t)(bb1*NHEADS + h) * SEQLEN + pos1) * DHEAD + d);
            if (z == 2) {
                __half h00 = __float2half(v00), h01 = __float2half(v01);
                __half h10 = __float2half(v10), h11 = __float2half(v11);
                __half2 hp0; hp0.x = h00; hp0.y = h01;
                __half2 hp1; hp1.x = h10; hp1.y = h11;
                *(__half2*)(g_vhf + base0) = hp0;
                *(__half2*)(g_vhf + base1) = hp1;
                __half2 lp0, lp1;
                lp0.x = __float2half((v00 - __half2float(h00)) * SPLIT_SC);
                lp0.y = __float2half((v01 - __half2float(h01)) * SPLIT_SC);
                lp1.x = __float2half((v10 - __half2float(h10)) * SPLIT_SC);
                lp1.y = __float2half((v11 - __half2float(h11)) * SPLIT_SC);
                *(__half2*)(g_vlf + base0) = lp0;
                *(__half2*)(g_vlf + base1) = lp1;
            } else {
                const int p = (col & 127) >> 1;
                float cs0 = g_cos[pos0*64 + p], sn0 = g_sin[pos0*64 + p];
                float cs1 = g_cos[pos1*64 + p], sn1 = g_sin[pos1*64 + p];
                const float sc = (z == 0) ? QK_SCALE : 1.0f;
                float x1 = v00, x2 = v01;
                v00 = (x1*cs0 - x2*sn0) * sc;  v01 = (x1*sn0 + x2*cs0) * sc;
                x1 = v10; x2 = v11;
                v10 = (x1*cs1 - x2*sn1) * sc;  v11 = (x1*sn1 + x2*cs1) * sc;
                __nv_bfloat16* dhi = (z == 0) ? g_qhi : g_khi;
                __nv_bfloat16* dlo = (z == 0) ? g_qlo : g_klo;
                __nv_bfloat16 h00 = __float2bfloat16(v00), h01 = __float2bfloat16(v01);
                __nv_bfloat16 h10 = __float2bfloat16(v10), h11 = __float2bfloat16(v11);
                __nv_bfloat162 hp0; hp0.x = h00; hp0.y = h01;
                __nv_bfloat162 hp1; hp1.x = h10; hp1.y = h11;
                *(__nv_bfloat162*)(dhi + base0) = hp0;
                *(__nv_bfloat162*)(dhi + base1) = hp1;
                __nv_bfloat162 lp0, lp1;
                lp0.x = __float2bfloat16(v00 - __bfloat162float(h00));
                lp0.y = __float2bfloat16(v01 - __bfloat162float(h01));
                lp1.x = __float2bfloat16(v10 - __bfloat162float(h10));
                lp1.y = __float2bfloat16(v11 - __bfloat162float(h11));
                *(__nv_bfloat162*)(dlo + base0) = lp0;
                *(__nv_bfloat162*)(dlo + base1) = lp1;
            }
        }
    }
}

// ---- output projection: 2-term fp16 ------------------------------------------------
__global__ void __launch_bounds__(256, 2)
out_mma(const float* __restrict__ bias, float* __restrict__ outp)
{
    extern __shared__ __nv_bfloat16 smem[];
    const int m0 = blockIdx.y * 128;
    const int n0 = blockIdx.x * 128;

    GemmCore core;
    core.init(smem_u32(smem), m0, n0, g_af, g_as, g_wfh[1], g_wfl[1]);

    float acc[2][8][4];
    #pragma unroll
    for (int i = 0; i < 2; i++)
        #pragma unroll
        for (int j = 0; j < 8; j++)
            #pragma unroll
            for (int k = 0; k < 4; k++) acc[i][j][k] = 0.f;

    core.run<2>(acc);

    const int g = core.lane >> 2, t = core.lane & 3;
    #pragma unroll
    for (int mf = 0; mf < 2; mf++) {
        const int r0 = m0 + core.wm*32 + mf*16 + g;
        const int r1 = r0 + 8;
        #pragma unroll
        for (int nf = 0; nf < 8; nf++) {
            const int col = n0 + core.wn*64 + nf*8 + 2*t;
            float b0 = bias[col], b1 = bias[col + 1];
            *(float2*)(outp + (size_t)r0 * 2048 + col) =
                make_float2(acc[mf][nf][0] + b0, acc[mf][nf][1] + b1);
            *(float2*)(outp + (size_t)r1 * 2048 + col) =
                make_float2(acc[mf][nf][2] + b0, acc[mf][nf][3] + b1);
        }
    }
}

// ---------------- flash attention: QK 3-term bf16, PV 2-term fp16, occ 2 -----------
#define AKVLD 136
#define A_SUB 8704
#define A_KH(b) ((b)*2*A_SUB)
#define A_KL(b) ((b)*2*A_SUB + A_SUB)
#define A_VH   (4*A_SUB)
#define A_VL   (5*A_SUB)
#define SM_ATTN_BYTES (6*A_SUB*2)        // 104448 B

__global__ void __launch_bounds__(128, 2)
attn_mma()
{
    extern __shared__ __nv_bfloat16 smn[];
    const uint32_t sb = smem_u32(smn);
    const int tid = threadIdx.x, lane = tid & 31, w = tid >> 5;
    const int bh = blockIdx.y;
    const int qt = 31 - blockIdx.x;
    const int q0 = qt * 64;

    const size_t qoff = ((size_t)bh * SEQLEN + q0) * DHEAD;
    for (int idx = tid; idx < 1024; idx += 128) {
        int row = idx >> 4, c = idx & 15;
        uint32_t off = (uint32_t)(row * AKVLD + c * 8) * 2;
        cp16(sb + A_KH(0)*2 + off, g_qhi + qoff + row * 128 + c * 8);
        cp16(sb + A_KL(0)*2 + off, g_qlo + qoff + row * 128 + c * 8);
    }
    CP_COMMIT(); CP_WAIT(0);
    __syncthreads();

    uint32_t qh[8][4], ql[8][4];
    const int lr = lane & 15, lhb = lane >> 4;
    #pragma unroll
    for (int kk = 0; kk < 8; kk++) {
        uint32_t ra = sb + (uint32_t)((w*16 + lr) * AKVLD + kk*16 + lhb*8) * 2;
        ldm_x4(qh[kk], ra + A_KH(0)*2);
        ldm_x4(ql[kk], ra + A_KL(0)*2);
    }
    __syncthreads();

    auto load_K = [&](int jt, int buf) {
        const size_t koff = ((size_t)bh * SEQLEN + jt * 64) * DHEAD;
        for (int idx = tid; idx < 1024; idx += 128) {
            int row = idx >> 4, c = idx & 15;
            uint32_t off = (uint32_t)(row * AKVLD + c * 8) * 2;
            int so = row * 128 + c * 8;
            cp16(sb + A_KH(buf)*2 + off, g_khi + koff + so);
            cp16(sb + A_KL(buf)*2 + off, g_klo + koff + so);
        }
    };
    auto load_V = [&](int jt) {
        const size_t koff = ((size_t)bh * SEQLEN + jt * 64) * DHEAD;
        for (int idx = tid; idx < 1024; idx += 128) {
            int row = idx >> 4, c = idx & 15;
            uint32_t off = (uint32_t)(row * AKVLD + c * 8) * 2;
            int so = row * 128 + c * 8;
            cp16(sb + A_VH*2 + off, g_vhf + koff + so);
            cp16(sb + A_VL*2 + off, g_vlf + koff + so);
        }
    };

    float m_[2] = {-INFINITY, -INFINITY};
    float l_[2] = {0.f, 0.f};
    float o[16][4];
    #pragma unroll
    for (int i = 0; i < 16; i++)
        #pragma unroll
        for (int j = 0; j < 4; j++) o[i][j] = 0.f;

    const int g  = lane >> 2, t2 = (lane & 3) * 2;
    const int wrow0 = q0 + w * 16;
    const int row0  = wrow0 + g;

    const int ntiles = qt + 1;
    load_K(0, 0); CP_COMMIT();
    load_V(0);    CP_COMMIT();

    for (int jt = 0; jt < ntiles; jt++) {
        const int kbuf = jt & 1;
        const int kv0 = jt * 64;
        const bool more = (jt + 1 < ntiles);

        if (more) { load_K(jt + 1, kbuf ^ 1); CP_COMMIT(); }
        if (more) CP_WAIT(2); else CP_WAIT(1);
        __syncthreads();

        const uint32_t kb = sb + A_KH(kbuf) * 2;

        // ---- S = Q K^T (3-term bf16) ----
        float s[8][4];
        #pragma unroll
        for (int i = 0; i < 8; i++)
            #pragma unroll
            for (int j = 0; j < 4; j++) s[i][j] = 0.f;

        #pragma unroll
        for (int kk = 0; kk < 8; kk++) {
            #pragma unroll
            for (int nb = 0; nb < 4; nb++) {
                uint32_t kh4[4], kl4[4];
                uint32_t rb = kb + (uint32_t)((nb*16 + lr) * AKVLD + kk*16 + lhb*8) * 2;
                ldm_x4(kh4, rb);
                ldm_x4(kl4, rb + A_SUB*2);
                #pragma unroll
                for (int sub = 0; sub < 2; sub++) {
                    float* c = s[nb*2 + sub];
                    mma_bf16(c, qh[kk], kh4[sub], kh4[sub+2]);
                    mma_bf16(c, qh[kk], kl4[sub], kl4[sub+2]);
                    mma_bf16(c, ql[kk], kh4[sub], kh4[sub+2]);
                }
            }
        }

        if (kv0 + 63 > wrow0) {
            #pragma unroll
            for (int nf = 0; nf < 8; nf++) {
                int c0 = kv0 + nf*8 + t2;
                if (c0     > row0)     s[nf][0] = -1e30f;
                if (c0 + 1 > row0)     s[nf][1] = -1e30f;
                if (c0     > row0 + 8) s[nf][2] = -1e30f;
                if (c0 + 1 > row0 + 8) s[nf][3] = -1e30f;
            }
        }

        float mx0 = -INFINITY, mx1 = -INFINITY;
        #pragma unroll
        for (int nf = 0; nf < 8; nf++) {
            mx0 = fmaxf(mx0, fmaxf(s[nf][0], s[nf][1]));
            mx1 = fmaxf(mx1, fmaxf(s[nf][2], s[nf][3]));
        }
        mx0 = fmaxf(mx0, __shfl_xor_sync(0xffffffffu, mx0, 1));
        mx0 = fmaxf(mx0, __shfl_xor_sync(0xffffffffu, mx0, 2));
        mx1 = fmaxf(mx1, __shfl_xor_sync(0xffffffffu, mx1, 1));
        mx1 = fmaxf(mx1, __shfl_xor_sync(0xffffffffu, mx1, 2));
        float mn0 = fmaxf(m_[0], mx0), mn1 = fmaxf(m_[1], mx1);
        float f0 = __expf(m_[0] - mn0), f1 = __expf(m_[1] - mn1);
        m_[0] = mn0; m_[1] = mn1;

        float sum0 = 0.f, sum1 = 0.f;
        #pragma unroll
        for (int nf = 0; nf < 8; nf++) {
            s[nf][0] = __expf(s[nf][0] - mn0); sum0 += s[nf][0];
            s[nf][1] = __expf(s[nf][1] - mn0); sum0 += s[nf][1];
            s[nf][2] = __expf(s[nf][2] - mn1); sum1 += s[nf][2];
            s[nf][3] = __expf(s[nf][3] - mn1); sum1 += s[nf][3];
        }
        sum0 += __shfl_xor_sync(0xffffffffu, sum0, 1);
        sum0 += __shfl_xor_sync(0xffffffffu, sum0, 2);
        sum1 += __shfl_xor_sync(0xffffffffu, sum1, 1);
        sum1 += __shfl_xor_sync(0xffffffffu, sum1, 2);
        l_[0] = l_[0] * f0 + sum0;
        l_[1] = l_[1] * f1 + sum1;

        #pragma unroll
        for (int nf = 0; nf < 16; nf++) {
            o[nf][0] *= f0; o[nf][1] *= f0;
            o[nf][2] *= f1; o[nf][3] *= f1;
        }

        // ---- pack P (fp16 + scaled copy) as A-frags ----
        uint32_t pf[4][4], ps[4][4];
        #pragma unroll
        for (int kf = 0; kf < 4; kf++) {
            #pragma unroll
            for (int j = 0; j < 4; j++) {
                int nf = 2*kf + (j >> 1);
                int c0 = (j & 1) * 2;
                float p0 = s[nf][c0], p1 = s[nf][c0 + 1];
                pf[kf][j] = packh2(p0, p1);
                ps[kf][j] = packh2(p0 * SPLIT_SCI, p1 * SPLIT_SCI);
            }
        }

        if (more) CP_WAIT(1); else CP_WAIT(0);
        __syncthreads();

        // ---- O += P V (2-term fp16: pf*Vh + ps*Vl') ----
        const uint32_t vbase = sb + A_VH * 2;
        const int matv = lane >> 3, jv = lane & 7;
        #pragma unroll
        for (int kf = 0; kf < 4; kf++) {
            #pragma unroll
            for (int ng = 0; ng < 8; ng++) {
                uint32_t vh4[4], vl4[4];
                uint32_t va = vbase + (uint32_t)((kf*16 + jv + ((matv & 1) << 3)) * AKVLD
                                                + ng*16 + ((matv >> 1) << 3)) * 2;
                ldm_x4_t(vh4, va);
                ldm_x4_t(vl4, va + A_SUB*2);
                #pragma unroll
                for (int sub = 0; sub < 2; sub++) {
                    float* c = o[ng*2 + sub];
                    mma_fp16(c, pf[kf], vh4[sub*2], vh4[sub*2+1]);
                    mma_fp16(c, ps[kf], vl4[sub*2], vl4[sub*2+1]);
                }
            }
        }
        __syncthreads();
        if (more) { load_V(jt + 1); CP_COMMIT(); }
    }

    // ---- epilogue: normalize, write fp16 + scaled fp16 (x-layout) ----
    const float inv0 = 1.f / l_[0];
    const float inv1 = 1.f / l_[1];
    const int bb = bh >> 4, h = bh & 15;
    const size_t rA0 = (size_t)(bb * SEQLEN + row0) * D_MODEL + h * DHEAD;
    const size_t rA1 = rA0 + 8 * D_MODEL;
    #pragma unroll
    for (int nf = 0; nf < 16; nf++) {
        int d = nf*8 + t2;
        float v00 = o[nf][0]*inv0, v01 = o[nf][1]*inv0;
        float v10 = o[nf][2]*inv1, v11 = o[nf][3]*inv1;
        __half2 f0h = __floats2half2_rn(v00, v01);
        __half2 f1h = __floats2half2_rn(v10, v11);
        *(__half2*)(g_af + rA0 + d) = f0h;
        *(__half2*)(g_af + rA1 + d) = f1h;
        __half2 s0h = __floats2half2_rn(v00 * SPLIT_SCI, v01 * SPLIT_SCI);
        __half2 s1h = __floats2half2_rn(v10 * SPLIT_SCI, v11 * SPLIT_SCI);
        *(__half2*)(g_as + rA0 + d) = s0h;
        *(__half2*)(g_as + rA1 + d) = s1h;
    }
}

// ---------------- launch -----------------------------------------------------------
extern "C" void kernel_launch(void* const* d_in, const int* in_sizes, int n_in,
                              void* d_out, int out_size)
{
    const float* x  = (const float*)d_in[0];
    const float* Wq = (const float*)d_in[1];
    const float* bq = (const float*)d_in[2];
    const float* Wk = (const float*)d_in[3];
    const float* bk = (const float*)d_in[4];
    const float* Wv = (const float*)d_in[5];
    const float* bv = (const float*)d_in[6];
    const float* Wo = (const float*)d_in[7];
    const float* bo = (const float*)d_in[8];
    float* out = (float*)d_out;

    cudaFuncSetAttribute(attn_mma, cudaFuncAttributeMaxDynamicSharedMemorySize, SM_ATTN_BYTES);
    cudaFuncSetAttribute(qkv_mma,  cudaFuncAttributeMaxDynamicSharedMemorySize, SMEM_GEMM_BYTES);
    cudaFuncSetAttribute(out_mma,  cudaFuncAttributeMaxDynamicSharedMemorySize, SMEM_GEMM_BYTES);

    rope_table_kernel<<<512, 256>>>();

    const int NX = MROWS * D_MODEL;
    const int NW = D_MODEL * D_MODEL;
    split_x_kernel<<<NX/256, 256>>>(x);
    split_w_kernel<<<dim3(NW/256, 4), 256>>>(Wq, Wk, Wv, Wo);

    qkv_mma<<<dim3(16, 32, 3), 256, SMEM_GEMM_BYTES>>>(bq, bk, bv);

    attn_mma<<<dim3(32, 32), 128, SM_ATTN_BYTES>>>();

    out_mma<<<dim3(16, 32), 256, SMEM_GEMM_BYTES>>>(bo, out);
}

// round 12
// speedup vs baseline: 1.3180x; 1.0944x over previous
#include <cuda_runtime.h>
#include <cuda_fp16.h>
#include <math.h>
#include <stdint.h>

#define D_MODEL 2048
#define NHEADS  16
#define DHEAD   128
#define SEQLEN  2048
#define BATCH   2
#define MROWS   (BATCH*SEQLEN)   // 4096
#define QK_SCALE 0.08838834764831845f   // 1/sqrt(128)
#define SPLIT_SC 2048.0f                // 2^11 scaled-correction factor
#define SPLIT_SCI (1.0f/2048.0f)

// ---------------- scratch (device globals; no allocation allowed) ----------------
__device__ float g_cos[SEQLEN*(DHEAD/2)];
__device__ float g_sin[SEQLEN*(DHEAD/2)];

// fp16 2-term everywhere.  A-side of a GEMM: (value, value/2048).
// B-side: (value_f, (value - value_f)*2048).
__device__ __half g_xf[MROWS*D_MODEL];                // fp16(x)
__device__ __half g_xs[MROWS*D_MODEL];                // fp16(x/2048)
__device__ __half g_wfh[4][D_MODEL*D_MODEL];          // 0=Wq 1=Wk 2=Wv 3=Wo : fp16(W)
__device__ __half g_wfl[4][D_MODEL*D_MODEL];          // fp16((W-hi)*2048)
__device__ __half g_qf[BATCH*NHEADS*SEQLEN*DHEAD];    // fp16(q·scale)   (A-side of QK^T)
__device__ __half g_qs[BATCH*NHEADS*SEQLEN*DHEAD];    // fp16(q·scale/2048)
__device__ __half g_kf[BATCH*NHEADS*SEQLEN*DHEAD];    // fp16(k)         (B-side of QK^T)
__device__ __half g_kr[BATCH*NHEADS*SEQLEN*DHEAD];    // fp16((k-kf)*2048)
__device__ __half g_vhf[BATCH*NHEADS*SEQLEN*DHEAD];   // fp16(v)         (B-side of PV)
__device__ __half g_vlf[BATCH*NHEADS*SEQLEN*DHEAD];   // fp16((v-vh)*2048)
__device__ __half g_af[MROWS*D_MODEL];                // fp16(attn out)  (A-side of out-proj)
__device__ __half g_as[MROWS*D_MODEL];                // fp16(attn out/2048)

// ---------------- PTX helpers (sm_80-level only) -----------------------------------
__device__ __forceinline__ uint32_t smem_u32(const void* p) {
    uint32_t a;
    asm("{ .reg .u64 t; cvta.to.shared.u64 t, %1; cvt.u32.u64 %0, t; }" : "=r"(a) : "l"(p));
    return a;
}
__device__ __forceinline__ void cp16(uint32_t dst, const void* src) {
    asm volatile("cp.async.cg.shared.global [%0], [%1], 16;" :: "r"(dst), "l"(src));
}
#define CP_COMMIT() asm volatile("cp.async.commit_group;" ::: "memory")
#define CP_WAIT(n)  asm volatile("cp.async.wait_group %0;" :: "n"(n) : "memory")

__device__ __forceinline__ void ldm_x4(uint32_t* r, uint32_t addr) {
    asm volatile("ldmatrix.sync.aligned.m8n8.x4.shared.b16 {%0,%1,%2,%3}, [%4];"
                 : "=r"(r[0]), "=r"(r[1]), "=r"(r[2]), "=r"(r[3]) : "r"(addr));
}
__device__ __forceinline__ void ldm_x4_t(uint32_t* r, uint32_t addr) {
    asm volatile("ldmatrix.sync.aligned.m8n8.x4.trans.shared.b16 {%0,%1,%2,%3}, [%4];"
                 : "=r"(r[0]), "=r"(r[1]), "=r"(r[2]), "=r"(r[3]) : "r"(addr));
}
__device__ __forceinline__ void mma_fp16(float* c, const uint32_t* a, uint32_t b0, uint32_t b1) {
    asm volatile("mma.sync.aligned.m16n8k16.row.col.f32.f16.f16.f32 "
                 "{%0,%1,%2,%3}, {%4,%5,%6,%7}, {%8,%9}, {%0,%1,%2,%3};"
                 : "+f"(c[0]), "+f"(c[1]), "+f"(c[2]), "+f"(c[3])
                 : "r"(a[0]), "r"(a[1]), "r"(a[2]), "r"(a[3]), "r"(b0), "r"(b1));
}
__device__ __forceinline__ uint32_t packh2(float lo, float hi) {   // fp16x2, first asm src -> upper
    uint32_t r;
    asm("cvt.rn.f16x2.f32 %0, %1, %2;" : "=r"(r) : "f"(hi), "f"(lo));
    return r;
}

// ---------------- RoPE tables ------------------------------------------------------
__global__ void rope_table_kernel() {
    int idx = blockIdx.x * blockDim.x + threadIdx.x;
    int pos = idx >> 6;
    int p   = idx & 63;
    double freq = exp(-((double)(2 * p) / 128.0) * log(10000.0));
    double ang  = (double)pos * freq;
    g_cos[idx] = (float)cos(ang);
    g_sin[idx] = (float)sin(ang);
}

// ---------------- split kernels ----------------------------------------------------
__global__ void split_x_kernel(const float* __restrict__ src) {
    int i = blockIdx.x * 256 + threadIdx.x;
    float v = src[i];
    g_xf[i] = __float2half(v);
    g_xs[i] = __float2half(v * SPLIT_SCI);
}
// grid (NW/256, 4): 0=Wq 1=Wk 2=Wv 3=Wo, all fp16 2-term (B-side form)
__global__ void split_w_kernel(const float* __restrict__ w0, const float* __restrict__ w1,
                               const float* __restrict__ w2, const float* __restrict__ w3) {
    int i = blockIdx.x * 256 + threadIdx.x;
    int wsel = blockIdx.y;
    const float* s = (wsel == 0) ? w0 : (wsel == 1) ? w1 : (wsel == 2) ? w2 : w3;
    float v = s[i];
    __half h = __float2half(v);
    g_wfh[wsel][i] = h;
    g_wfl[wsel][i] = __float2half((v - __half2float(h)) * SPLIT_SC);
}

// ---------------- GEMM core: BM=BN=128, BK=16, 8 warps, 4-stage, occ 2 -------------
// 2-term fp16: acc = A0*B0 + A1*B1  (A0=a, A1=a/2048, B0=b_f, B1=res*2048)
#define GLD 24
#define T_A0 0
#define T_A1 (128*GLD)
#define T_B0 (2*128*GLD)
#define T_B1 (3*128*GLD)
#define STAGE_HALVES (4*128*GLD)              // 24576 B
#define SMEM_GEMM_BYTES (4*STAGE_HALVES*2)    // 98304 B

struct GemmCore {
    uint32_t sb;
    int lane, wm, wn, lrow, lc, lr, lh;
    const uint16_t *pA0, *pA1, *pB0, *pB1;

    __device__ __forceinline__ void init(uint32_t sb_, int m0, int n0,
                                         const void* A0, const void* A1,
                                         const void* B0, const void* B1) {
        sb = sb_;
        int tid = threadIdx.x;
        lane = tid & 31;
        int warp = tid >> 5;
        wm = warp & 3; wn = warp >> 2;
        lrow = tid & 127; lc = tid >> 7;
        lr = lane & 15; lh = lane >> 4;
        pA0 = (const uint16_t*)A0 + (size_t)(m0 + lrow) * 2048;
        pA1 = (const uint16_t*)A1 + (size_t)(m0 + lrow) * 2048;
        pB0 = (const uint16_t*)B0 + (size_t)(n0 + lrow) * 2048;
        pB1 = (const uint16_t*)B1 + (size_t)(n0 + lrow) * 2048;
    }
    __device__ __forceinline__ void load_stage(int s, int buf) {
        const int ks = s * 16 + lc * 8;
        const uint32_t base = sb + buf * STAGE_HALVES * 2;
        const uint32_t off = (lrow * GLD + lc * 8) * 2;
        cp16(base + T_A0*2 + off, pA0 + ks);
        cp16(base + T_A1*2 + off, pA1 + ks);
        cp16(base + T_B0*2 + off, pB0 + ks);
        cp16(base + T_B1*2 + off, pB1 + ks);
    }
    __device__ __forceinline__ void run(float acc[2][8][4]) {
        load_stage(0, 0); CP_COMMIT();
        load_stage(1, 1); CP_COMMIT();
        load_stage(2, 2); CP_COMMIT();
        for (int s = 0; s < 128; s++) {
            const int rem = 127 - s;
            if      (rem >= 2) CP_WAIT(2);
            else if (rem == 1) CP_WAIT(1);
            else               CP_WAIT(0);
            __syncthreads();
            const uint32_t base = sb + (s & 3) * STAGE_HALVES * 2;
            uint32_t a0[2][4], a1[2][4], b0[4][4], b1[4][4];
            #pragma unroll
            for (int mf = 0; mf < 2; mf++) {
                uint32_t ra = base + ((wm*32 + mf*16 + lr) * GLD + lh*8) * 2;
                ldm_x4(a0[mf], ra + T_A0*2);
                ldm_x4(a1[mf], ra + T_A1*2);
            }
            #pragma unroll
            for (int nb = 0; nb < 4; nb++) {
                uint32_t rb = base + ((wn*64 + nb*16 + lr) * GLD + lh*8) * 2;
                ldm_x4(b0[nb], rb + T_B0*2);
                ldm_x4(b1[nb], rb + T_B1*2);
            }
            #pragma unroll
            for (int mf = 0; mf < 2; mf++)
                #pragma unroll
                for (int nb = 0; nb < 4; nb++)
                    #pragma unroll
                    for (int sub = 0; sub < 2; sub++) {
                        float* c = acc[mf][nb*2 + sub];
                        mma_fp16(c, a0[mf], b0[nb][sub], b0[nb][sub+2]);
                        mma_fp16(c, a1[mf], b1[nb][sub], b1[nb][sub+2]);
                    }
            if (s + 3 < 128) { load_stage(s + 3, (s + 3) & 3); CP_COMMIT(); }
        }
    }
};

// ---- fused Q/K/V projection: grid (16, 32, 3), z: 0=Q 1=K 2=V, all 2-term fp16 ----
__global__ void __launch_bounds__(256, 2)
qkv_mma(const float* __restrict__ bq, const float* __restrict__ bk,
        const float* __restrict__ bv)
{
    extern __shared__ __half smem[];
    const int m0 = blockIdx.y * 128;
    const int n0 = blockIdx.x * 128;
    const int z  = blockIdx.z;

    GemmCore core;
    core.init(smem_u32(smem), m0, n0, g_xf, g_xs, g_wfh[z], g_wfl[z]);

    float acc[2][8][4];
    #pragma unroll
    for (int i = 0; i < 2; i++)
        #pragma unroll
        for (int j = 0; j < 8; j++)
            #pragma unroll
            for (int k = 0; k < 4; k++) acc[i][j][k] = 0.f;

    core.run(acc);

    const float* bias = (z == 0) ? bq : (z == 1) ? bk : bv;
    const int g = core.lane >> 2, t = core.lane & 3;
    #pragma unroll
    for (int mf = 0; mf < 2; mf++) {
        const int r0 = m0 + core.wm*32 + mf*16 + g;
        const int r1 = r0 + 8;
        const int bb0 = r0 >> 11, pos0 = r0 & 2047;
        const int bb1 = r1 >> 11, pos1 = r1 & 2047;
        #pragma unroll
        for (int nf = 0; nf < 8; nf++) {
            const int col = n0 + core.wn*64 + nf*8 + 2*t;
            float b0 = bias[col], b1 = bias[col + 1];
            float v00 = acc[mf][nf][0] + b0, v01 = acc[mf][nf][1] + b1;
            float v10 = acc[mf][nf][2] + b0, v11 = acc[mf][nf][3] + b1;
            const int h = col >> 7, d = col & 127;
            size_t base0 = (((size_t)(bb0*NHEADS + h) * SEQLEN + pos0) * DHEAD + d);
            size_t base1 = (((size_t)(bb1*NHEADS + h) * SEQLEN + pos1) * DHEAD + d);
            if (z == 2) {
                // V: B-side form (value, residual*2048)
                __half h00 = __float2half(v00), h01 = __float2half(v01);
                __half h10 = __float2half(v10), h11 = __float2half(v11);
                __half2 hp0; hp0.x = h00; hp0.y = h01;
                __half2 hp1; hp1.x = h10; hp1.y = h11;
                *(__half2*)(g_vhf + base0) = hp0;
                *(__half2*)(g_vhf + base1) = hp1;
                __half2 lp0, lp1;
                lp0.x = __float2half((v00 - __half2float(h00)) * SPLIT_SC);
                lp0.y = __float2half((v01 - __half2float(h01)) * SPLIT_SC);
                lp1.x = __float2half((v10 - __half2float(h10)) * SPLIT_SC);
                lp1.y = __float2half((v11 - __half2float(h11)) * SPLIT_SC);
                *(__half2*)(g_vlf + base0) = lp0;
                *(__half2*)(g_vlf + base1) = lp1;
            } else {
                // Q/K: RoPE (+scale for Q)
                const int p = (col & 127) >> 1;
                float cs0 = g_cos[pos0*64 + p], sn0 = g_sin[pos0*64 + p];
                float cs1 = g_cos[pos1*64 + p], sn1 = g_sin[pos1*64 + p];
                const float sc = (z == 0) ? QK_SCALE : 1.0f;
                float x1 = v00, x2 = v01;
                v00 = (x1*cs0 - x2*sn0) * sc;  v01 = (x1*sn0 + x2*cs0) * sc;
                x1 = v10; x2 = v11;
                v10 = (x1*cs1 - x2*sn1) * sc;  v11 = (x1*sn1 + x2*cs1) * sc;
                if (z == 0) {
                    // Q: A-side form (value, value/2048)
                    __half2 f0 = __floats2half2_rn(v00, v01);
                    __half2 f1 = __floats2half2_rn(v10, v11);
                    *(__half2*)(g_qf + base0) = f0;
                    *(__half2*)(g_qf + base1) = f1;
                    __half2 s0 = __floats2half2_rn(v00 * SPLIT_SCI, v01 * SPLIT_SCI);
                    __half2 s1 = __floats2half2_rn(v10 * SPLIT_SCI, v11 * SPLIT_SCI);
                    *(__half2*)(g_qs + base0) = s0;
                    *(__half2*)(g_qs + base1) = s1;
                } else {
                    // K: B-side form (value, residual*2048)
                    __half h00 = __float2half(v00), h01 = __float2half(v01);
                    __half h10 = __float2half(v10), h11 = __float2half(v11);
                    __half2 hp0; hp0.x = h00; hp0.y = h01;
                    __half2 hp1; hp1.x = h10; hp1.y = h11;
                    *(__half2*)(g_kf + base0) = hp0;
                    *(__half2*)(g_kf + base1) = hp1;
                    __half2 lp0, lp1;
                    lp0.x = __float2half((v00 - __half2float(h00)) * SPLIT_SC);
                    lp0.y = __float2half((v01 - __half2float(h01)) * SPLIT_SC);
                    lp1.x = __float2half((v10 - __half2float(h10)) * SPLIT_SC);
                    lp1.y = __float2half((v11 - __half2float(h11)) * SPLIT_SC);
                    *(__half2*)(g_kr + base0) = lp0;
                    *(__half2*)(g_kr + base1) = lp1;
                }
            }
        }
    }
}

// ---- output projection: 2-term fp16 ------------------------------------------------
__global__ void __launch_bounds__(256, 2)
out_mma(const float* __restrict__ bias, float* __restrict__ outp)
{
    extern __shared__ __half smem[];
    const int m0 = blockIdx.y * 128;
    const int n0 = blockIdx.x * 128;

    GemmCore core;
    core.init(smem_u32(smem), m0, n0, g_af, g_as, g_wfh[3], g_wfl[3]);

    float acc[2][8][4];
    #pragma unroll
    for (int i = 0; i < 2; i++)
        #pragma unroll
        for (int j = 0; j < 8; j++)
            #pragma unroll
            for (int k = 0; k < 4; k++) acc[i][j][k] = 0.f;

    core.run(acc);

    const int g = core.lane >> 2, t = core.lane & 3;
    #pragma unroll
    for (int mf = 0; mf < 2; mf++) {
        const int r0 = m0 + core.wm*32 + mf*16 + g;
        const int r1 = r0 + 8;
        #pragma unroll
        for (int nf = 0; nf < 8; nf++) {
            const int col = n0 + core.wn*64 + nf*8 + 2*t;
            float b0 = bias[col], b1 = bias[col + 1];
            *(float2*)(outp + (size_t)r0 * 2048 + col) =
                make_float2(acc[mf][nf][0] + b0, acc[mf][nf][1] + b1);
            *(float2*)(outp + (size_t)r1 * 2048 + col) =
                make_float2(acc[mf][nf][2] + b0, acc[mf][nf][3] + b1);
        }
    }
}

// ---------------- flash attention: all 2-term fp16, occ 2 --------------------------
#define AKVLD 136
#define A_SUB 8704
#define A_KH(b) ((b)*2*A_SUB)
#define A_KL(b) ((b)*2*A_SUB + A_SUB)
#define A_VH   (4*A_SUB)
#define A_VL   (5*A_SUB)
#define SM_ATTN_BYTES (6*A_SUB*2)        // 104448 B

__global__ void __launch_bounds__(128, 2)
attn_mma()
{
    extern __shared__ __half smn[];
    const uint32_t sb = smem_u32(smn);
    const int tid = threadIdx.x, lane = tid & 31, w = tid >> 5;
    const int bh = blockIdx.y;
    const int qt = 31 - blockIdx.x;
    const int q0 = qt * 64;

    const size_t qoff = ((size_t)bh * SEQLEN + q0) * DHEAD;
    for (int idx = tid; idx < 1024; idx += 128) {
        int row = idx >> 4, c = idx & 15;
        uint32_t off = (uint32_t)(row * AKVLD + c * 8) * 2;
        cp16(sb + A_KH(0)*2 + off, g_qf + qoff + row * 128 + c * 8);
        cp16(sb + A_KL(0)*2 + off, g_qs + qoff + row * 128 + c * 8);
    }
    CP_COMMIT(); CP_WAIT(0);
    __syncthreads();

    uint32_t qf[8][4], qs[8][4];
    const int lr = lane & 15, lhb = lane >> 4;
    #pragma unroll
    for (int kk = 0; kk < 8; kk++) {
        uint32_t ra = sb + (uint32_t)((w*16 + lr) * AKVLD + kk*16 + lhb*8) * 2;
        ldm_x4(qf[kk], ra + A_KH(0)*2);
        ldm_x4(qs[kk], ra + A_KL(0)*2);
    }
    __syncthreads();

    auto load_K = [&](int jt, int buf) {
        const size_t koff = ((size_t)bh * SEQLEN + jt * 64) * DHEAD;
        for (int idx = tid; idx < 1024; idx += 128) {
            int row = idx >> 4, c = idx & 15;
            uint32_t off = (uint32_t)(row * AKVLD + c * 8) * 2;
            int so = row * 128 + c * 8;
            cp16(sb + A_KH(buf)*2 + off, g_kf + koff + so);
            cp16(sb + A_KL(buf)*2 + off, g_kr + koff + so);
        }
    };
    auto load_V = [&](int jt) {
        const size_t koff = ((size_t)bh * SEQLEN + jt * 64) * DHEAD;
        for (int idx = tid; idx < 1024; idx += 128) {
            int row = idx >> 4, c = idx & 15;
            uint32_t off = (uint32_t)(row * AKVLD + c * 8) * 2;
            int so = row * 128 + c * 8;
            cp16(sb + A_VH*2 + off, g_vhf + koff + so);
            cp16(sb + A_VL*2 + off, g_vlf + koff + so);
        }
    };

    float m_[2] = {-INFINITY, -INFINITY};
    float l_[2] = {0.f, 0.f};
    float o[16][4];
    #pragma unroll
    for (int i = 0; i < 16; i++)
        #pragma unroll
        for (int j = 0; j < 4; j++) o[i][j] = 0.f;

    const int g  = lane >> 2, t2 = (lane & 3) * 2;
    const int wrow0 = q0 + w * 16;
    const int row0  = wrow0 + g;

    const int ntiles = qt + 1;
    load_K(0, 0); CP_COMMIT();
    load_V(0);    CP_COMMIT();

    for (int jt = 0; jt < ntiles; jt++) {
        const int kbuf = jt & 1;
        const int kv0 = jt * 64;
        const bool more = (jt + 1 < ntiles);

        if (more) { load_K(jt + 1, kbuf ^ 1); CP_COMMIT(); }
        if (more) CP_WAIT(2); else CP_WAIT(1);
        __syncthreads();

        const uint32_t kb = sb + A_KH(kbuf) * 2;

        // ---- S = Q K^T (2-term fp16: qf*Kf + qs*Kr) ----
        float s[8][4];
        #pragma unroll
        for (int i = 0; i < 8; i++)
            #pragma unroll
            for (int j = 0; j < 4; j++) s[i][j] = 0.f;

        #pragma unroll
        for (int kk = 0; kk < 8; kk++) {
            #pragma unroll
            for (int nb = 0; nb < 4; nb++) {
                uint32_t kf4[4], kr4[4];
                uint32_t rb = kb + (uint32_t)((nb*16 + lr) * AKVLD + kk*16 + lhb*8) * 2;
                ldm_x4(kf4, rb);
                ldm_x4(kr4, rb + A_SUB*2);
                #pragma unroll
                for (int sub = 0; sub < 2; sub++) {
                    float* c = s[nb*2 + sub];
                    mma_fp16(c, qf[kk], kf4[sub], kf4[sub+2]);
                    mma_fp16(c, qs[kk], kr4[sub], kr4[sub+2]);
                }
            }
        }

        if (kv0 + 63 > wrow0) {
            #pragma unroll
            for (int nf = 0; nf < 8; nf++) {
                int c0 = kv0 + nf*8 + t2;
                if (c0     > row0)     s[nf][0] = -1e30f;
                if (c0 + 1 > row0)     s[nf][1] = -1e30f;
                if (c0     > row0 + 8) s[nf][2] = -1e30f;
                if (c0 + 1 > row0 + 8) s[nf][3] = -1e30f;
            }
        }

        float mx0 = -INFINITY, mx1 = -INFINITY;
        #pragma unroll
        for (int nf = 0; nf < 8; nf++) {
            mx0 = fmaxf(mx0, fmaxf(s[nf][0], s[nf][1]));
            mx1 = fmaxf(mx1, fmaxf(s[nf][2], s[nf][3]));
        }
        mx0 = fmaxf(mx0, __shfl_xor_sync(0xffffffffu, mx0, 1));
        mx0 = fmaxf(mx0, __shfl_xor_sync(0xffffffffu, mx0, 2));
        mx1 = fmaxf(mx1, __shfl_xor_sync(0xffffffffu, mx1, 1));
        mx1 = fmaxf(mx1, __shfl_xor_sync(0xffffffffu, mx1, 2));
        float mn0 = fmaxf(m_[0], mx0), mn1 = fmaxf(m_[1], mx1);
        float f0 = __expf(m_[0] - mn0), f1 = __expf(m_[1] - mn1);
        m_[0] = mn0; m_[1] = mn1;

        float sum0 = 0.f, sum1 = 0.f;
        #pragma unroll
        for (int nf = 0; nf < 8; nf++) {
            s[nf][0] = __expf(s[nf][0] - mn0); sum0 += s[nf][0];
            s[nf][1] = __expf(s[nf][1] - mn0); sum0 += s[nf][1];
            s[nf][2] = __expf(s[nf][2] - mn1); sum1 += s[nf][2];
            s[nf][3] = __expf(s[nf][3] - mn1); sum1 += s[nf][3];
        }
        sum0 += __shfl_xor_sync(0xffffffffu, sum0, 1);
        sum0 += __shfl_xor_sync(0xffffffffu, sum0, 2);
        sum1 += __shfl_xor_sync(0xffffffffu, sum1, 1);
        sum1 += __shfl_xor_sync(0xffffffffu, sum1, 2);
        l_[0] = l_[0] * f0 + sum0;
        l_[1] = l_[1] * f1 + sum1;

        #pragma unroll
        for (int nf = 0; nf < 16; nf++) {
            o[nf][0] *= f0; o[nf][1] *= f0;
            o[nf][2] *= f1; o[nf][3] *= f1;
        }

        // ---- pack P (fp16 + /2048 copy) as A-frags ----
        uint32_t pf[4][4], ps[4][4];
        #pragma unroll
        for (int kf2 = 0; kf2 < 4; kf2++) {
            #pragma unroll
            for (int j = 0; j < 4; j++) {
                int nf = 2*kf2 + (j >> 1);
                int c0 = (j & 1) * 2;
                float p0 = s[nf][c0], p1 = s[nf][c0 + 1];
                pf[kf2][j] = packh2(p0, p1);
                ps[kf2][j] = packh2(p0 * SPLIT_SCI, p1 * SPLIT_SCI);
            }
        }

        if (more) CP_WAIT(1); else CP_WAIT(0);
        __syncthreads();

        // ---- O += P V (2-term fp16) ----
        const uint32_t vbase = sb + A_VH * 2;
        const int matv = lane >> 3, jv = lane & 7;
        #pragma unroll
        for (int kf2 = 0; kf2 < 4; kf2++) {
            #pragma unroll
            for (int ng = 0; ng < 8; ng++) {
                uint32_t vh4[4], vl4[4];
                uint32_t va = vbase + (uint32_t)((kf2*16 + jv + ((matv & 1) << 3)) * AKVLD
                                                + ng*16 + ((matv >> 1) << 3)) * 2;
                ldm_x4_t(vh4, va);
                ldm_x4_t(vl4, va + A_SUB*2);
                #pragma unroll
                for (int sub = 0; sub < 2; sub++) {
                    float* c = o[ng*2 + sub];
                    mma_fp16(c, pf[kf2], vh4[sub*2], vh4[sub*2+1]);
                    mma_fp16(c, ps[kf2], vl4[sub*2], vl4[sub*2+1]);
                }
            }
        }
        __syncthreads();
        if (more) { load_V(jt + 1); CP_COMMIT(); }
    }

    // ---- epilogue: normalize, write fp16 + /2048 fp16 (x-layout) ----
    const float inv0 = 1.f / l_[0];
    const float inv1 = 1.f / l_[1];
    const int bb = bh >> 4, h = bh & 15;
    const size_t rA0 = (size_t)(bb * SEQLEN + row0) * D_MODEL + h * DHEAD;
    const size_t rA1 = rA0 + 8 * D_MODEL;
    #pragma unroll
    for (int nf = 0; nf < 16; nf++) {
        int d = nf*8 + t2;
        float v00 = o[nf][0]*inv0, v01 = o[nf][1]*inv0;
        float v10 = o[nf][2]*inv1, v11 = o[nf][3]*inv1;
        __half2 f0h = __floats2half2_rn(v00, v01);
        __half2 f1h = __floats2half2_rn(v10, v11);
        *(__half2*)(g_af + rA0 + d) = f0h;
        *(__half2*)(g_af + rA1 + d) = f1h;
        __half2 s0h = __floats2half2_rn(v00 * SPLIT_SCI, v01 * SPLIT_SCI);
        __half2 s1h = __floats2half2_rn(v10 * SPLIT_SCI, v11 * SPLIT_SCI);
        *(__half2*)(g_as + rA0 + d) = s0h;
        *(__half2*)(g_as + rA1 + d) = s1h;
    }
}

// ---------------- launch -----------------------------------------------------------
extern "C" void kernel_launch(void* const* d_in, const int* in_sizes, int n_in,
                              void* d_out, int out_size)
{
    const float* x  = (const float*)d_in[0];
    const float* Wq = (const float*)d_in[1];
    const float* bq = (const float*)d_in[2];
    const float* Wk = (const float*)d_in[3];
    const float* bk = (const float*)d_in[4];
    const float* Wv = (const float*)d_in[5];
    const float* bv = (const float*)d_in[6];
    const float* Wo = (const float*)d_in[7];
    const float* bo = (const float*)d_in[8];
    float* out = (float*)d_out;

    cudaFuncSetAttribute(attn_mma, cudaFuncAttributeMaxDynamicSharedMemorySize, SM_ATTN_BYTES);
    cudaFuncSetAttribute(qkv_mma,  cudaFuncAttributeMaxDynamicSharedMemorySize, SMEM_GEMM_BYTES);
    cudaFuncSetAttribute(out_mma,  cudaFuncAttributeMaxDynamicSharedMemorySize, SMEM_GEMM_BYTES);

    rope_table_kernel<<<512, 256>>>();

    const int NX = MROWS * D_MODEL;
    const int NW = D_MODEL * D_MODEL;
    split_x_kernel<<<NX/256, 256>>>(x);
    split_w_kernel<<<dim3(NW/256, 4), 256>>>(Wq, Wk, Wv, Wo);

    qkv_mma<<<dim3(16, 32, 3), 256, SMEM_GEMM_BYTES>>>(bq, bk, bv);

    attn_mma<<<dim3(32, 32), 128, SM_ATTN_BYTES>>>();

    out_mma<<<dim3(16, 32), 256, SMEM_GEMM_BYTES>>>(bo, out);
}

// round 13
// speedup vs baseline: 1.6058x; 1.2183x over previous
#include <cuda_runtime.h>
#include <cuda_fp16.h>
#include <math.h>
#include <stdint.h>

#define D_MODEL 2048
#define NHEADS  16
#define DHEAD   128
#define SEQLEN  2048
#define BATCH   2
#define MROWS   (BATCH*SEQLEN)   // 4096
#define QK_SCALE 0.08838834764831845f   // 1/sqrt(128)
#define SPLIT_SC 2048.0f                // 2^11 scaled-correction factor
#define SPLIT_SCI (1.0f/2048.0f)

// ---------------- scratch (device globals; no allocation allowed) ----------------
__device__ float g_cos[SEQLEN*(DHEAD/2)];
__device__ float g_sin[SEQLEN*(DHEAD/2)];

// fp16 2-term.  A-side: single tensor (A1 = A0 * 2^-11 computed in registers).
// B-side: (value_f, (value - value_f)*2048).
__device__ __half g_xf[MROWS*D_MODEL];                // fp16(x)
__device__ __half g_wfh[4][D_MODEL*D_MODEL];          // 0=Wq 1=Wk 2=Wv 3=Wo : fp16(W)
__device__ __half g_wfl[4][D_MODEL*D_MODEL];          // fp16((W-hi)*2048)
__device__ __half g_qf[BATCH*NHEADS*SEQLEN*DHEAD];    // fp16(q·scale)   (A-side of QK^T)
__device__ __half g_kf[BATCH*NHEADS*SEQLEN*DHEAD];    // fp16(k)         (B-side of QK^T)
__device__ __half g_kr[BATCH*NHEADS*SEQLEN*DHEAD];    // fp16((k-kf)*2048)
__device__ __half g_vhf[BATCH*NHEADS*SEQLEN*DHEAD];   // fp16(v)         (B-side of PV)
__device__ __half g_vlf[BATCH*NHEADS*SEQLEN*DHEAD];   // fp16((v-vh)*2048)
__device__ __half g_af[MROWS*D_MODEL];                // fp16(attn out)  (A-side of out-proj)

// ---------------- PTX helpers (sm_80-level only) -----------------------------------
__device__ __forceinline__ uint32_t smem_u32(const void* p) {
    uint32_t a;
    asm("{ .reg .u64 t; cvta.to.shared.u64 t, %1; cvt.u32.u64 %0, t; }" : "=r"(a) : "l"(p));
    return a;
}
__device__ __forceinline__ void cp16(uint32_t dst, const void* src) {
    asm volatile("cp.async.cg.shared.global [%0], [%1], 16;" :: "r"(dst), "l"(src));
}
#define CP_COMMIT() asm volatile("cp.async.commit_group;" ::: "memory")
#define CP_WAIT(n)  asm volatile("cp.async.wait_group %0;" :: "n"(n) : "memory")

__device__ __forceinline__ void ldm_x4(uint32_t* r, uint32_t addr) {
    asm volatile("ldmatrix.sync.aligned.m8n8.x4.shared.b16 {%0,%1,%2,%3}, [%4];"
                 : "=r"(r[0]), "=r"(r[1]), "=r"(r[2]), "=r"(r[3]) : "r"(addr));
}
__device__ __forceinline__ void ldm_x4_t(uint32_t* r, uint32_t addr) {
    asm volatile("ldmatrix.sync.aligned.m8n8.x4.trans.shared.b16 {%0,%1,%2,%3}, [%4];"
                 : "=r"(r[0]), "=r"(r[1]), "=r"(r[2]), "=r"(r[3]) : "r"(addr));
}
__device__ __forceinline__ void mma_fp16(float* c, const uint32_t* a, uint32_t b0, uint32_t b1) {
    asm volatile("mma.sync.aligned.m16n8k16.row.col.f32.f16.f16.f32 "
                 "{%0,%1,%2,%3}, {%4,%5,%6,%7}, {%8,%9}, {%0,%1,%2,%3};"
                 : "+f"(c[0]), "+f"(c[1]), "+f"(c[2]), "+f"(c[3])
                 : "r"(a[0]), "r"(a[1]), "r"(a[2]), "r"(a[3]), "r"(b0), "r"(b1));
}
__device__ __forceinline__ uint32_t packh2(float lo, float hi) {   // fp16x2, first asm src -> upper
    uint32_t r;
    asm("cvt.rn.f16x2.f32 %0, %1, %2;" : "=r"(r) : "f"(hi), "f"(lo));
    return r;
}
__device__ __forceinline__ uint32_t h2scale(uint32_t v, uint32_t sc2) {  // fp16x2 * fp16x2
    uint32_t r;
    asm("mul.rn.f16x2 %0, %1, %2;" : "=r"(r) : "r"(v), "r"(sc2));
    return r;
}
#define SCI_H2 0x10001000u   // fp16x2 {2^-11, 2^-11}  (0x1000 = 2^-11 in fp16)

// ---------------- RoPE tables ------------------------------------------------------
__global__ void rope_table_kernel() {
    int idx = blockIdx.x * blockDim.x + threadIdx.x;
    int pos = idx >> 6;
    int p   = idx & 63;
    double freq = exp(-((double)(2 * p) / 128.0) * log(10000.0));
    double ang  = (double)pos * freq;
    g_cos[idx] = (float)cos(ang);
    g_sin[idx] = (float)sin(ang);
}

// ---------------- split kernels ----------------------------------------------------
__global__ void split_x_kernel(const float* __restrict__ src) {
    int i = blockIdx.x * 256 + threadIdx.x;
    g_xf[i] = __float2half(src[i]);
}
__global__ void split_w_kernel(const float* __restrict__ w0, const float* __restrict__ w1,
                               const float* __restrict__ w2, const float* __restrict__ w3) {
    int i = blockIdx.x * 256 + threadIdx.x;
    int wsel = blockIdx.y;
    const float* s = (wsel == 0) ? w0 : (wsel == 1) ? w1 : (wsel == 2) ? w2 : w3;
    float v = s[i];
    __half h = __float2half(v);
    g_wfh[wsel][i] = h;
    g_wfl[wsel][i] = __float2half((v - __half2float(h)) * SPLIT_SC);
}

// ---------------- GEMM core: BM=BN=128, BK=16, 8 warps, 4-stage, occ 2 -------------
// 2-term fp16: acc = A*B0 + (A*2^-11)*B1 ; A1 fragments derived in registers.
#define GLD 24
#define T_A0 0
#define T_B0 (128*GLD)
#define T_B1 (2*128*GLD)
#define STAGE_HALVES (3*128*GLD)              // 9216 halves = 18432 B
#define SMEM_GEMM_BYTES (4*STAGE_HALVES*2)    // 73728 B

struct GemmCore {
    uint32_t sb;
    int lane, wm, wn, lrow, lc, lr, lh;
    const uint16_t *pA0, *pB0, *pB1;

    __device__ __forceinline__ void init(uint32_t sb_, int m0, int n0,
                                         const void* A0, const void* B0, const void* B1) {
        sb = sb_;
        int tid = threadIdx.x;
        lane = tid & 31;
        int warp = tid >> 5;
        wm = warp & 3; wn = warp >> 2;
        lrow = tid & 127; lc = tid >> 7;
        lr = lane & 15; lh = lane >> 4;
        pA0 = (const uint16_t*)A0 + (size_t)(m0 + lrow) * 2048;
        pB0 = (const uint16_t*)B0 + (size_t)(n0 + lrow) * 2048;
        pB1 = (const uint16_t*)B1 + (size_t)(n0 + lrow) * 2048;
    }
    __device__ __forceinline__ void load_stage(int s, int buf) {
        const int ks = s * 16 + lc * 8;
        const uint32_t base = sb + buf * STAGE_HALVES * 2;
        const uint32_t off = (lrow * GLD + lc * 8) * 2;
        cp16(base + T_A0*2 + off, pA0 + ks);
        cp16(base + T_B0*2 + off, pB0 + ks);
        cp16(base + T_B1*2 + off, pB1 + ks);
    }
    __device__ __forceinline__ void run(float acc[2][8][4]) {
        load_stage(0, 0); CP_COMMIT();
        load_stage(1, 1); CP_COMMIT();
        load_stage(2, 2); CP_COMMIT();
        for (int s = 0; s < 128; s++) {
            const int rem = 127 - s;
            if      (rem >= 2) CP_WAIT(2);
            else if (rem == 1) CP_WAIT(1);
            else               CP_WAIT(0);
            __syncthreads();
            const uint32_t base = sb + (s & 3) * STAGE_HALVES * 2;
            uint32_t a0[2][4], a1[2][4], b0[4][4], b1[4][4];
            #pragma unroll
            for (int mf = 0; mf < 2; mf++) {
                uint32_t ra = base + ((wm*32 + mf*16 + lr) * GLD + lh*8) * 2;
                ldm_x4(a0[mf], ra + T_A0*2);
                #pragma unroll
                for (int j = 0; j < 4; j++) a1[mf][j] = h2scale(a0[mf][j], SCI_H2);
            }
            #pragma unroll
            for (int nb = 0; nb < 4; nb++) {
                uint32_t rb = base + ((wn*64 + nb*16 + lr) * GLD + lh*8) * 2;
                ldm_x4(b0[nb], rb + T_B0*2);
                ldm_x4(b1[nb], rb + T_B1*2);
            }
            #pragma unroll
            for (int mf = 0; mf < 2; mf++)
                #pragma unroll
                for (int nb = 0; nb < 4; nb++)
                    #pragma unroll
                    for (int sub = 0; sub < 2; sub++) {
                        float* c = acc[mf][nb*2 + sub];
                        mma_fp16(c, a0[mf], b0[nb][sub], b0[nb][sub+2]);
                        mma_fp16(c, a1[mf], b1[nb][sub], b1[nb][sub+2]);
                    }
            if (s + 3 < 128) { load_stage(s + 3, (s + 3) & 3); CP_COMMIT(); }
        }
    }
};

// ---- fused Q/K/V projection: grid (16, 32, 3), z: 0=Q 1=K 2=V ---------------------
__global__ void __launch_bounds__(256, 2)
qkv_mma(const float* __restrict__ bq, const float* __restrict__ bk,
        const float* __restrict__ bv)
{
    extern __shared__ __half smem[];
    const int m0 = blockIdx.y * 128;
    const int n0 = blockIdx.x * 128;
    const int z  = blockIdx.z;

    GemmCore core;
    core.init(smem_u32(smem), m0, n0, g_xf, g_wfh[z], g_wfl[z]);

    float acc[2][8][4];
    #pragma unroll
    for (int i = 0; i < 2; i++)
        #pragma unroll
        for (int j = 0; j < 8; j++)
            #pragma unroll
            for (int k = 0; k < 4; k++) acc[i][j][k] = 0.f;

    core.run(acc);

    const float* bias = (z == 0) ? bq : (z == 1) ? bk : bv;
    const int g = core.lane >> 2, t = core.lane & 3;
    #pragma unroll
    for (int mf = 0; mf < 2; mf++) {
        const int r0 = m0 + core.wm*32 + mf*16 + g;
        const int r1 = r0 + 8;
        const int bb0 = r0 >> 11, pos0 = r0 & 2047;
        const int bb1 = r1 >> 11, pos1 = r1 & 2047;
        #pragma unroll
        for (int nf = 0; nf < 8; nf++) {
            const int col = n0 + core.wn*64 + nf*8 + 2*t;
            float b0 = bias[col], b1 = bias[col + 1];
            float v00 = acc[mf][nf][0] + b0, v01 = acc[mf][nf][1] + b1;
            float v10 = acc[mf][nf][2] + b0, v11 = acc[mf][nf][3] + b1;
            const int h = col >> 7, d = col & 127;
            size_t base0 = (((size_t)(bb0*NHEADS + h) * SEQLEN + pos0) * DHEAD + d);
            size_t base1 = (((size_t)(bb1*NHEADS + h) * SEQLEN + pos1) * DHEAD + d);
            if (z == 2) {
                // V: B-side form (value, residual*2048)
                __half h00 = __float2half(v00), h01 = __float2half(v01);
                __half h10 = __float2half(v10), h11 = __float2half(v11);
                __half2 hp0; hp0.x = h00; hp0.y = h01;
                __half2 hp1; hp1.x = h10; hp1.y = h11;
                *(__half2*)(g_vhf + base0) = hp0;
                *(__half2*)(g_vhf + base1) = hp1;
                __half2 lp0, lp1;
                lp0.x = __float2half((v00 - __half2float(h00)) * SPLIT_SC);
                lp0.y = __float2half((v01 - __half2float(h01)) * SPLIT_SC);
                lp1.x = __float2half((v10 - __half2float(h10)) * SPLIT_SC);
                lp1.y = __float2half((v11 - __half2float(h11)) * SPLIT_SC);
                *(__half2*)(g_vlf + base0) = lp0;
                *(__half2*)(g_vlf + base1) = lp1;
            } else {
                const int p = (col & 127) >> 1;
                float cs0 = g_cos[pos0*64 + p], sn0 = g_sin[pos0*64 + p];
                float cs1 = g_cos[pos1*64 + p], sn1 = g_sin[pos1*64 + p];
                const float sc = (z == 0) ? QK_SCALE : 1.0f;
                float x1 = v00, x2 = v01;
                v00 = (x1*cs0 - x2*sn0) * sc;  v01 = (x1*sn0 + x2*cs0) * sc;
                x1 = v10; x2 = v11;
                v10 = (x1*cs1 - x2*sn1) * sc;  v11 = (x1*sn1 + x2*cs1) * sc;
                if (z == 0) {
                    // Q: A-side form, single tensor
                    *(__half2*)(g_qf + base0) = __floats2half2_rn(v00, v01);
                    *(__half2*)(g_qf + base1) = __floats2half2_rn(v10, v11);
                } else {
                    // K: B-side form (value, residual*2048)
                    __half h00 = __float2half(v00), h01 = __float2half(v01);
                    __half h10 = __float2half(v10), h11 = __float2half(v11);
                    __half2 hp0; hp0.x = h00; hp0.y = h01;
                    __half2 hp1; hp1.x = h10; hp1.y = h11;
                    *(__half2*)(g_kf + base0) = hp0;
                    *(__half2*)(g_kf + base1) = hp1;
                    __half2 lp0, lp1;
                    lp0.x = __float2half((v00 - __half2float(h00)) * SPLIT_SC);
                    lp0.y = __float2half((v01 - __half2float(h01)) * SPLIT_SC);
                    lp1.x = __float2half((v10 - __half2float(h10)) * SPLIT_SC);
                    lp1.y = __float2half((v11 - __half2float(h11)) * SPLIT_SC);
                    *(__half2*)(g_kr + base0) = lp0;
                    *(__half2*)(g_kr + base1) = lp1;
                }
            }
        }
    }
}

// ---- output projection -------------------------------------------------------------
__global__ void __launch_bounds__(256, 2)
out_mma(const float* __restrict__ bias, float* __restrict__ outp)
{
    extern __shared__ __half smem[];
    const int m0 = blockIdx.y * 128;
    const int n0 = blockIdx.x * 128;

    GemmCore core;
    core.init(smem_u32(smem), m0, n0, g_af, g_wfh[3], g_wfl[3]);

    float acc[2][8][4];
    #pragma unroll
    for (int i = 0; i < 2; i++)
        #pragma unroll
        for (int j = 0; j < 8; j++)
            #pragma unroll
            for (int k = 0; k < 4; k++) acc[i][j][k] = 0.f;

    core.run(acc);

    const int g = core.lane >> 2, t = core.lane & 3;
    #pragma unroll
    for (int mf = 0; mf < 2; mf++) {
        const int r0 = m0 + core.wm*32 + mf*16 + g;
        const int r1 = r0 + 8;
        #pragma unroll
        for (int nf = 0; nf < 8; nf++) {
            const int col = n0 + core.wn*64 + nf*8 + 2*t;
            float b0 = bias[col], b1 = bias[col + 1];
            *(float2*)(outp + (size_t)r0 * 2048 + col) =
                make_float2(acc[mf][nf][0] + b0, acc[mf][nf][1] + b1);
            *(float2*)(outp + (size_t)r1 * 2048 + col) =
                make_float2(acc[mf][nf][2] + b0, acc[mf][nf][3] + b1);
        }
    }
}

// ---------------- flash attention: 2-term fp16, A1-from-regs, occ 2 ----------------
#define AKVLD 136
#define A_SUB 8704
#define A_KH(b) ((b)*2*A_SUB)
#define A_KL(b) ((b)*2*A_SUB + A_SUB)
#define A_VH   (4*A_SUB)
#define A_VL   (5*A_SUB)
#define SM_ATTN_BYTES (6*A_SUB*2)        // 104448 B

__global__ void __launch_bounds__(128, 2)
attn_mma()
{
    extern __shared__ __half smn[];
    const uint32_t sb = smem_u32(smn);
    const int tid = threadIdx.x, lane = tid & 31, w = tid >> 5;
    const int bh = blockIdx.y;
    const int qt = 31 - blockIdx.x;
    const int q0 = qt * 64;

    // stage Q (qf only) into K-buffer 0 area
    const size_t qoff = ((size_t)bh * SEQLEN + q0) * DHEAD;
    for (int idx = tid; idx < 1024; idx += 128) {
        int row = idx >> 4, c = idx & 15;
        uint32_t off = (uint32_t)(row * AKVLD + c * 8) * 2;
        cp16(sb + A_KH(0)*2 + off, g_qf + qoff + row * 128 + c * 8);
    }
    CP_COMMIT(); CP_WAIT(0);
    __syncthreads();

    uint32_t qf[8][4], qs[8][4];
    const int lr = lane & 15, lhb = lane >> 4;
    #pragma unroll
    for (int kk = 0; kk < 8; kk++) {
        uint32_t ra = sb + (uint32_t)((w*16 + lr) * AKVLD + kk*16 + lhb*8) * 2;
        ldm_x4(qf[kk], ra + A_KH(0)*2);
        #pragma unroll
        for (int j = 0; j < 4; j++) qs[kk][j] = h2scale(qf[kk][j], SCI_H2);
    }
    __syncthreads();

    auto load_K = [&](int jt, int buf) {
        const size_t koff = ((size_t)bh * SEQLEN + jt * 64) * DHEAD;
        for (int idx = tid; idx < 1024; idx += 128) {
            int row = idx >> 4, c = idx & 15;
            uint32_t off = (uint32_t)(row * AKVLD + c * 8) * 2;
            int so = row * 128 + c * 8;
            cp16(sb + A_KH(buf)*2 + off, g_kf + koff + so);
            cp16(sb + A_KL(buf)*2 + off, g_kr + koff + so);
        }
    };
    auto load_V = [&](int jt) {
        const size_t koff = ((size_t)bh * SEQLEN + jt * 64) * DHEAD;
        for (int idx = tid; idx < 1024; idx += 128) {
            int row = idx >> 4, c = idx & 15;
            uint32_t off = (uint32_t)(row * AKVLD + c * 8) * 2;
            int so = row * 128 + c * 8;
            cp16(sb + A_VH*2 + off, g_vhf + koff + so);
            cp16(sb + A_VL*2 + off, g_vlf + koff + so);
        }
    };

    float m_[2] = {-INFINITY, -INFINITY};
    float l_[2] = {0.f, 0.f};
    float o[16][4];
    #pragma unroll
    for (int i = 0; i < 16; i++)
        #pragma unroll
        for (int j = 0; j < 4; j++) o[i][j] = 0.f;

    const int g  = lane >> 2, t2 = (lane & 3) * 2;
    const int wrow0 = q0 + w * 16;
    const int row0  = wrow0 + g;

    const int ntiles = qt + 1;
    load_K(0, 0); CP_COMMIT();
    load_V(0);    CP_COMMIT();

    for (int jt = 0; jt < ntiles; jt++) {
        const int kbuf = jt & 1;
        const int kv0 = jt * 64;
        const bool more = (jt + 1 < ntiles);

        if (more) { load_K(jt + 1, kbuf ^ 1); CP_COMMIT(); }
        if (more) CP_WAIT(2); else CP_WAIT(1);
        __syncthreads();

        const uint32_t kb = sb + A_KH(kbuf) * 2;

        // ---- S = Q K^T (qf*Kf + qs*Kr) ----
        float s[8][4];
        #pragma unroll
        for (int i = 0; i < 8; i++)
            #pragma unroll
            for (int j = 0; j < 4; j++) s[i][j] = 0.f;

        #pragma unroll
        for (int kk = 0; kk < 8; kk++) {
            #pragma unroll
            for (int nb = 0; nb < 4; nb++) {
                uint32_t kf4[4], kr4[4];
                uint32_t rb = kb + (uint32_t)((nb*16 + lr) * AKVLD + kk*16 + lhb*8) * 2;
                ldm_x4(kf4, rb);
                ldm_x4(kr4, rb + A_SUB*2);
                #pragma unroll
                for (int sub = 0; sub < 2; sub++) {
                    float* c = s[nb*2 + sub];
                    mma_fp16(c, qf[kk], kf4[sub], kf4[sub+2]);
                    mma_fp16(c, qs[kk], kr4[sub], kr4[sub+2]);
                }
            }
        }

        if (kv0 + 63 > wrow0) {
            #pragma unroll
            for (int nf = 0; nf < 8; nf++) {
                int c0 = kv0 + nf*8 + t2;
                if (c0     > row0)     s[nf][0] = -1e30f;
                if (c0 + 1 > row0)     s[nf][1] = -1e30f;
                if (c0     > row0 + 8) s[nf][2] = -1e30f;
                if (c0 + 1 > row0 + 8) s[nf][3] = -1e30f;
            }
        }

        float mx0 = -INFINITY, mx1 = -INFINITY;
        #pragma unroll
        for (int nf = 0; nf < 8; nf++) {
            mx0 = fmaxf(mx0, fmaxf(s[nf][0], s[nf][1]));
            mx1 = fmaxf(mx1, fmaxf(s[nf][2], s[nf][3]));
        }
        mx0 = fmaxf(mx0, __shfl_xor_sync(0xffffffffu, mx0, 1));
        mx0 = fmaxf(mx0, __shfl_xor_sync(0xffffffffu, mx0, 2));
        mx1 = fmaxf(mx1, __shfl_xor_sync(0xffffffffu, mx1, 1));
        mx1 = fmaxf(mx1, __shfl_xor_sync(0xffffffffu, mx1, 2));
        float mn0 = fmaxf(m_[0], mx0), mn1 = fmaxf(m_[1], mx1);
        float f0 = __expf(m_[0] - mn0), f1 = __expf(m_[1] - mn1);
        m_[0] = mn0; m_[1] = mn1;

        float sum0 = 0.f, sum1 = 0.f;
        #pragma unroll
        for (int nf = 0; nf < 8; nf++) {
            s[nf][0] = __expf(s[nf][0] - mn0); sum0 += s[nf][0];
            s[nf][1] = __expf(s[nf][1] - mn0); sum0 += s[nf][1];
            s[nf][2] = __expf(s[nf][2] - mn1); sum1 += s[nf][2];
            s[nf][3] = __expf(s[nf][3] - mn1); sum1 += s[nf][3];
        }
        sum0 += __shfl_xor_sync(0xffffffffu, sum0, 1);
        sum0 += __shfl_xor_sync(0xffffffffu, sum0, 2);
        sum1 += __shfl_xor_sync(0xffffffffu, sum1, 1);
        sum1 += __shfl_xor_sync(0xffffffffu, sum1, 2);
        l_[0] = l_[0] * f0 + sum0;
        l_[1] = l_[1] * f1 + sum1;

        #pragma unroll
        for (int nf = 0; nf < 16; nf++) {
            o[nf][0] *= f0; o[nf][1] *= f0;
            o[nf][2] *= f1; o[nf][3] *= f1;
        }

        // ---- pack P + register-derived /2048 copy ----
        uint32_t pf[4][4], ps[4][4];
        #pragma unroll
        for (int kf2 = 0; kf2 < 4; kf2++) {
            #pragma unroll
            for (int j = 0; j < 4; j++) {
                int nf = 2*kf2 + (j >> 1);
                int c0 = (j & 1) * 2;
                pf[kf2][j] = packh2(s[nf][c0], s[nf][c0 + 1]);
                ps[kf2][j] = h2scale(pf[kf2][j], SCI_H2);
            }
        }

        if (more) CP_WAIT(1); else CP_WAIT(0);
        __syncthreads();

        // ---- O += P V (pf*Vh + ps*Vl') ----
        const uint32_t vbase = sb + A_VH * 2;
        const int matv = lane >> 3, jv = lane & 7;
        #pragma unroll
        for (int kf2 = 0; kf2 < 4; kf2++) {
            #pragma unroll
            for (int ng = 0; ng < 8; ng++) {
                uint32_t vh4[4], vl4[4];
                uint32_t va = vbase + (uint32_t)((kf2*16 + jv + ((matv & 1) << 3)) * AKVLD
                                                + ng*16 + ((matv >> 1) << 3)) * 2;
                ldm_x4_t(vh4, va);
                ldm_x4_t(vl4, va + A_SUB*2);
                #pragma unroll
                for (int sub = 0; sub < 2; sub++) {
                    float* c = o[ng*2 + sub];
                    mma_fp16(c, pf[kf2], vh4[sub*2], vh4[sub*2+1]);
                    mma_fp16(c, ps[kf2], vl4[sub*2], vl4[sub*2+1]);
                }
            }
        }
        __syncthreads();
        if (more) { load_V(jt + 1); CP_COMMIT(); }
    }

    // ---- epilogue: normalize, write fp16 A-side (x-layout) ----
    const float inv0 = 1.f / l_[0];
    const float inv1 = 1.f / l_[1];
    const int bb = bh >> 4, h = bh & 15;
    const size_t rA0 = (size_t)(bb * SEQLEN + row0) * D_MODEL + h * DHEAD;
    const size_t rA1 = rA0 + 8 * D_MODEL;
    #pragma unroll
    for (int nf = 0; nf < 16; nf++) {
        int d = nf*8 + t2;
        *(__half2*)(g_af + rA0 + d) = __floats2half2_rn(o[nf][0]*inv0, o[nf][1]*inv0);
        *(__half2*)(g_af + rA1 + d) = __floats2half2_rn(o[nf][2]*inv1, o[nf][3]*inv1);
    }
}

// ---------------- launch -----------------------------------------------------------
extern "C" void kernel_launch(void* const* d_in, const int* in_sizes, int n_in,
                              void* d_out, int out_size)
{
    const float* x  = (const float*)d_in[0];
    const float* Wq = (const float*)d_in[1];
    const float* bq = (const float*)d_in[2];
    const float* Wk = (const float*)d_in[3];
    const float* bk = (const float*)d_in[4];
    const float* Wv = (const float*)d_in[5];
    const float* bv = (const float*)d_in[6];
    const float* Wo = (const float*)d_in[7];
    const float* bo = (const float*)d_in[8];
    float* out = (float*)d_out;

    cudaFuncSetAttribute(attn_mma, cudaFuncAttributeMaxDynamicSharedMemorySize, SM_ATTN_BYTES);
    cudaFuncSetAttribute(qkv_mma,  cudaFuncAttributeMaxDynamicSharedMemorySize, SMEM_GEMM_BYTES);
    cudaFuncSetAttribute(out_mma,  cudaFuncAttributeMaxDynamicSharedMemorySize, SMEM_GEMM_BYTES);

    rope_table_kernel<<<512, 256>>>();

    const int NX = MROWS * D_MODEL;
    const int NW = D_MODEL * D_MODEL;
    split_x_kernel<<<NX/256, 256>>>(x);
    split_w_kernel<<<dim3(NW/256, 4), 256>>>(Wq, Wk, Wv, Wo);

    qkv_mma<<<dim3(16, 32, 3), 256, SMEM_GEMM_BYTES>>>(bq, bk, bv);

    attn_mma<<<dim3(32, 32), 128, SM_ATTN_BYTES>>>();

    out_mma<<<dim3(16, 32), 256, SMEM_GEMM_BYTES>>>(bo, out);
}